// round 4
// baseline (speedup 1.0000x reference)
#include <cuda_runtime.h>
#include <cuda_bf16.h>
#include <cstdint>

// ---------------------------------------------------------------------------
// Nystrom attention transformer layer. TF32 mma GEMMs, fused epilogues,
// permuted-K smem layout (paired LDS.64 fragment loads, XOR bank swizzle).
// ---------------------------------------------------------------------------

#define B_    4
#define N_    4096
#define DIM_  512
#define H_    8
#define DH_   64
#define M_    256
#define L_    16
#define ROWS_ (B_ * N_)          // 16384
#define BH_   (B_ * H_)          // 32

// ---------------- scratch (device globals) ----------------------------------
__device__ float g_ln  [ROWS_ * DIM_];
__device__ float g_q   [BH_ * N_ * DH_];
__device__ float g_k   [BH_ * N_ * DH_];
__device__ float g_v   [BH_ * N_ * DH_];
__device__ float g_ql  [BH_ * M_ * DH_];
__device__ float g_kl  [BH_ * M_ * DH_];
__device__ float g_a1  [BH_ * N_ * M_];
__device__ float g_a3  [BH_ * M_ * N_];     // sim3 exp; later reused for a1@a2inv
__device__ float g_a2  [BH_ * M_ * M_];
__device__ float g_z0  [BH_ * M_ * M_];
__device__ float g_z1  [BH_ * M_ * M_];
__device__ float g_t1  [BH_ * M_ * M_];
__device__ float g_t2  [BH_ * M_ * M_];
__device__ float g_t3  [BH_ * M_ * M_];
__device__ float g_a3v [BH_ * M_ * DH_];
__device__ float g_part[BH_ * 4 * M_ * DH_];
__device__ float g_rsum[BH_ * M_];
__device__ float g_ctx [ROWS_ * DIM_];
__device__ float g_max [2];

// ---------------- reductions -------------------------------------------------
__device__ __forceinline__ float blockReduceSum(float v, float* sh) {
    int tid = threadIdx.x;
    sh[tid] = v; __syncthreads();
    for (int s = 128; s > 0; s >>= 1) {
        if (tid < s) sh[tid] += sh[tid + s];
        __syncthreads();
    }
    float r = sh[0]; __syncthreads();
    return r;
}
__device__ __forceinline__ float blockReduceMax(float v, float* sh) {
    int tid = threadIdx.x;
    sh[tid] = v; __syncthreads();
    for (int s = 128; s > 0; s >>= 1) {
        if (tid < s) sh[tid] = fmaxf(sh[tid], sh[tid + s]);
        __syncthreads();
    }
    float r = sh[0]; __syncthreads();
    return r;
}

// ---------------- layernorm --------------------------------------------------
__global__ __launch_bounds__(256) void ln_kernel(
    const float* __restrict__ x, const float* __restrict__ w,
    const float* __restrict__ b)
{
    __shared__ float sh[256];
    long long r = blockIdx.x;
    const float* xr = x + r * DIM_;
    int tid = threadIdx.x;
    float v0 = xr[tid], v1 = xr[tid + 256];
    float s = blockReduceSum(v0 + v1, sh);
    float mu = s * (1.0f / DIM_);
    float d0 = v0 - mu, d1 = v1 - mu;
    float s2 = blockReduceSum(d0 * d0 + d1 * d1, sh);
    float inv = rsqrtf(s2 * (1.0f / DIM_) + 1e-5f);
    g_ln[r * DIM_ + tid]        = d0 * inv * w[tid] + b[tid];
    g_ln[r * DIM_ + tid + 256]  = d1 * inv * w[tid + 256] + b[tid + 256];
}

// ---------------- TF32 helpers ----------------------------------------------
__device__ __forceinline__ uint32_t f2tf(float f) {
    uint32_t r;
    asm("cvt.rna.tf32.f32 %0, %1;" : "=r"(r) : "f"(f));
    return r;
}
__device__ __forceinline__ void mma_tf32(
    float& c0, float& c1, float& c2, float& c3,
    uint32_t a0, uint32_t a1, uint32_t a2, uint32_t a3,
    uint32_t b0, uint32_t b1)
{
    asm volatile(
        "mma.sync.aligned.m16n8k8.row.col.f32.tf32.tf32.f32 "
        "{%0,%1,%2,%3}, {%4,%5,%6,%7}, {%8,%9}, {%0,%1,%2,%3};"
        : "+f"(c0), "+f"(c1), "+f"(c2), "+f"(c3)
        : "r"(a0), "r"(a1), "r"(a2), "r"(a3), "r"(b0), "r"(b1));
}

// Permuted-K layout for a 16-deep K tile: element (k, row) stored at
// col = pos(k) ^ ((row & 2) << 2), pos(k) = (k>>3)*8 + (k&3)*2 + ((k>>2)&1).
// A thread's fragment pair (k=kk+tg, k=kk+tg+4) sits at cols (kk+2tg, kk+2tg+1)
// pre-swizzle -> one LDS.64.
__device__ __forceinline__ int kpos(int k) {
    return ((k >> 3) << 3) + ((k & 3) * 2) + ((k >> 2) & 1);
}

// ---------------- main mma GEMM, BK=16 double-buffered -----------------------
// MODE 0: standard epilogue (alpha, bias, resid)
// MODE 1: qkv split epilogue (write q/k/v head-major, q scaled)
// MODE 2: ctx epilogue (write to [row, dim] context layout)
// SPLITK: blockIdx.z = bh*4 + split, Kdim = chunk length
#define BK2 16

template<int BM, int BN, bool TB, int MODE, bool SPLITK>
__global__ __launch_bounds__(256) void mma_gemm_kernel(
    const float* __restrict__ A, const float* __restrict__ B,
    float* __restrict__ C, int Ndim, int Kdim, int ldA, int ldB,
    long long sA, long long sB, long long sC,
    float alpha,
    const float* __restrict__ resid, float residScale,
    const float* __restrict__ residScalePtr,
    const float* __restrict__ bias)
{
    constexpr int TM = BM / 4;
    constexpr int TN = BN / 2;
    constexpr int MT = TM / 16;
    constexpr int NT = TN / 8;
    constexpr int CHA = (BM * BK2) / 1024;
    constexpr int CHB = (BK2 * BN) / 1024;

    __shared__ __align__(16) uint32_t As[2][BM][BK2];
    __shared__ __align__(16) uint32_t Bs[2][BN][BK2];

    int bz = blockIdx.z;
    long long aOff, bOff, cOff;
    if (SPLITK) {
        int bz0 = bz >> 2, sp = bz & 3;
        aOff = (long long)bz0 * sA + (long long)sp * Kdim;
        bOff = (long long)bz0 * sB + (long long)sp * Kdim * ldB;
        cOff = (long long)bz * sC;
    } else {
        aOff = (long long)bz * sA;
        bOff = (long long)bz * sB;
        cOff = (long long)bz * sC;
    }
    const float* Ab = A + aOff;
    const float* Bb = B + bOff;
    float*       Cb = C + cOff;
    const float* Rb = resid ? resid + cOff : nullptr;

    int n0 = blockIdx.x * BN;
    int m0 = blockIdx.y * BM;
    int tid  = threadIdx.x;
    int wid  = tid >> 5;
    int lane = tid & 31;
    int wm = wid >> 1, wn = wid & 1;
    int tm0 = wm * TM, tn0 = wn * TN;
    int g  = lane >> 2;
    int tg = lane & 3;
    int sw = (g & 2) << 2;          // thread-constant XOR swizzle (rows ≡ g mod 8)

    float acc[MT][NT][4];
    #pragma unroll
    for (int i = 0; i < MT; i++)
        #pragma unroll
        for (int j = 0; j < NT; j++)
            #pragma unroll
            for (int c = 0; c < 4; c++) acc[i][j][c] = 0.f;

    float4 rA[CHA], rB[CHB];

    auto loadA = [&](int k0) {
        #pragma unroll
        for (int c = 0; c < CHA; c++) {
            int e = (c * 256 + tid) * 4;
            int m = e >> 4, k = e & 15;
            rA[c] = *(const float4*)(Ab + (long long)(m0 + m) * ldA + k0 + k);
        }
    };
    auto loadB = [&](int k0) {
        #pragma unroll
        for (int c = 0; c < CHB; c++) {
            int e = (c * 256 + tid) * 4;
            if (TB) {
                int k = e & 15, n = e >> 4;
                rB[c] = *(const float4*)(Bb + (long long)(n0 + n) * ldB + k0 + k);
            } else {
                int k = e / BN, n = e % BN;
                rB[c] = *(const float4*)(Bb + (long long)(k0 + k) * ldB + n0 + n);
            }
        }
    };
    auto storeAB = [&](int p) {
        #pragma unroll
        for (int c = 0; c < CHA; c++) {
            int e = (c * 256 + tid) * 4;
            int m = e >> 4, k = e & 15;     // k multiple of 4
            int base = ((k >> 3) << 3) + ((k & 4) >> 2);
            int swm = (m & 2) << 2;
            uint32_t* row = As[p][m];
            row[(base + 0) ^ swm] = f2tf(rA[c].x);
            row[(base + 2) ^ swm] = f2tf(rA[c].y);
            row[(base + 4) ^ swm] = f2tf(rA[c].z);
            row[(base + 6) ^ swm] = f2tf(rA[c].w);
        }
        #pragma unroll
        for (int c = 0; c < CHB; c++) {
            int e = (c * 256 + tid) * 4;
            if (TB) {
                int k = e & 15, n = e >> 4;  // k multiple of 4
                int base = ((k >> 3) << 3) + ((k & 4) >> 2);
                int swn = (n & 2) << 2;
                uint32_t* row = Bs[p][n];
                row[(base + 0) ^ swn] = f2tf(rB[c].x);
                row[(base + 2) ^ swn] = f2tf(rB[c].y);
                row[(base + 4) ^ swn] = f2tf(rB[c].z);
                row[(base + 6) ^ swn] = f2tf(rB[c].w);
            } else {
                int k = e / BN, n = e % BN;  // n multiple of 4
                int pp = kpos(k);
                Bs[p][n + 0][pp ^ (((n + 0) & 2) << 2)] = f2tf(rB[c].x);
                Bs[p][n + 1][pp ^ (((n + 1) & 2) << 2)] = f2tf(rB[c].y);
                Bs[p][n + 2][pp ^ (((n + 2) & 2) << 2)] = f2tf(rB[c].z);
                Bs[p][n + 3][pp ^ (((n + 3) & 2) << 2)] = f2tf(rB[c].w);
            }
        }
    };

    loadA(0); loadB(0);
    storeAB(0);
    __syncthreads();
    int p = 0;
    int nIter = Kdim / BK2;
    for (int t = 0; t < nIter; t++) {
        bool more = (t + 1) < nIter;
        if (more) { loadA((t + 1) * BK2); loadB((t + 1) * BK2); }

        #pragma unroll
        for (int kk = 0; kk < BK2; kk += 8) {
            int col = (kk + 2 * tg) ^ sw;
            uint32_t af[MT][4], bf[NT][2];
            #pragma unroll
            for (int i = 0; i < MT; i++) {
                int mb = tm0 + i * 16;
                uint2 lo = *(const uint2*)&As[p][mb + g    ][col];
                uint2 hi = *(const uint2*)&As[p][mb + g + 8][col];
                af[i][0] = lo.x; af[i][1] = hi.x;
                af[i][2] = lo.y; af[i][3] = hi.y;
            }
            #pragma unroll
            for (int j = 0; j < NT; j++) {
                uint2 bb = *(const uint2*)&Bs[p][tn0 + j * 8 + g][col];
                bf[j][0] = bb.x; bf[j][1] = bb.y;
            }
            #pragma unroll
            for (int i = 0; i < MT; i++)
                #pragma unroll
                for (int j = 0; j < NT; j++)
                    mma_tf32(acc[i][j][0], acc[i][j][1], acc[i][j][2], acc[i][j][3],
                             af[i][0], af[i][1], af[i][2], af[i][3],
                             bf[j][0], bf[j][1]);
        }

        if (more) storeAB(1 - p);
        __syncthreads();
        p ^= 1;
    }

    // ---------------- epilogue ----------------
    float rs = residScalePtr ? *residScalePtr : residScale;
    #pragma unroll
    for (int i = 0; i < MT; i++) {
        int r0 = m0 + tm0 + i * 16 + g;
        int r1 = r0 + 8;
        #pragma unroll
        for (int j = 0; j < NT; j++) {
            int cc = n0 + tn0 + j * 8 + tg * 2;
            if (MODE == 0) {
                float2 bv = bias ? *(const float2*)(bias + cc) : make_float2(0.f, 0.f);
                float2 v0 = make_float2(alpha * acc[i][j][0] + bv.x,
                                        alpha * acc[i][j][1] + bv.y);
                float2 v1 = make_float2(alpha * acc[i][j][2] + bv.x,
                                        alpha * acc[i][j][3] + bv.y);
                if (Rb) {
                    float2 q0 = *(const float2*)(Rb + (long long)r0 * Ndim + cc);
                    float2 q1 = *(const float2*)(Rb + (long long)r1 * Ndim + cc);
                    v0.x += rs * q0.x; v0.y += rs * q0.y;
                    v1.x += rs * q1.x; v1.y += rs * q1.y;
                }
                *(float2*)(Cb + (long long)r0 * Ndim + cc) = v0;
                *(float2*)(Cb + (long long)r1 * Ndim + cc) = v1;
            } else if (MODE == 1) {
                int which = cc >> 9;
                int hc = cc & 511;
                int h = hc >> 6, d = hc & 63;
                float sc = (which == 0) ? 0.125f : 1.0f;
                float* dstbuf = (which == 0) ? g_q : (which == 1) ? g_k : g_v;
                #pragma unroll
                for (int rr = 0; rr < 2; rr++) {
                    int row = rr ? r1 : r0;
                    int b = row >> 12, nn = row & 4095;
                    long long dst = (((long long)((b << 3) + h)) * N_ + nn) * DH_ + d;
                    float2 v = rr ? make_float2(sc * acc[i][j][2], sc * acc[i][j][3])
                                  : make_float2(sc * acc[i][j][0], sc * acc[i][j][1]);
                    *(float2*)(dstbuf + dst) = v;
                }
            } else {
                int b = bz >> 3, h = bz & 7;
                *(float2*)(g_ctx + ((long long)(b * N_ + r0)) * DIM_ + h * DH_ + cc) =
                    make_float2(acc[i][j][0], acc[i][j][1]);
                *(float2*)(g_ctx + ((long long)(b * N_ + r1)) * DIM_ + h * DH_ + cc) =
                    make_float2(acc[i][j][2], acc[i][j][3]);
            }
        }
    }
}

// ---------------- sim GEMM (TB) with fused full-row softmax ------------------
// BM=64, BN=256 (= full landmark dim), Kdim multiple of 16 (here 64).
__global__ __launch_bounds__(256) void sim_softmax_kernel(
    const float* __restrict__ A, const float* __restrict__ Bm,
    float* __restrict__ C, int Kdim,
    long long sA, long long sB, long long sC)
{
    constexpr int BMs = 64, BNs = 256;
    __shared__ __align__(16) uint32_t As[BMs][BK2];
    __shared__ __align__(16) uint32_t Bs[BNs][BK2];
    __shared__ float redM[2][BMs];
    __shared__ float redS[2][BMs];

    int bz = blockIdx.z;
    const float* Ab = A + (long long)bz * sA;
    const float* Bb = Bm + (long long)bz * sB;
    float*       Cb = C + (long long)bz * sC;

    int m0 = blockIdx.y * BMs;
    int tid  = threadIdx.x;
    int wid  = tid >> 5;
    int lane = tid & 31;
    int wm = wid >> 1, wn = wid & 1;
    int tm0 = wm * 16, tn0 = wn * 128;
    int g  = lane >> 2;
    int tg = lane & 3;
    int sw = (g & 2) << 2;

    float acc[16][4];
    #pragma unroll
    for (int j = 0; j < 16; j++)
        #pragma unroll
        for (int c = 0; c < 4; c++) acc[j][c] = 0.f;

    for (int k0 = 0; k0 < Kdim; k0 += BK2) {
        {   // A: 64 x 16, one float4/thread
            int e = tid * 4;
            int m = e >> 4, k = e & 15;
            float4 a4 = *(const float4*)(Ab + (long long)(m0 + m) * Kdim + k0 + k);
            int base = ((k >> 3) << 3) + ((k & 4) >> 2);
            int swm = (m & 2) << 2;
            uint32_t* row = As[m];
            row[(base + 0) ^ swm] = f2tf(a4.x);
            row[(base + 2) ^ swm] = f2tf(a4.y);
            row[(base + 4) ^ swm] = f2tf(a4.z);
            row[(base + 6) ^ swm] = f2tf(a4.w);
        }
        #pragma unroll
        for (int c = 0; c < 4; c++) {   // B: 256 x 16
            int e = (c * 256 + tid) * 4;
            int n = e >> 4, k = e & 15;
            float4 b4 = *(const float4*)(Bb + (long long)n * Kdim + k0 + k);
            int base = ((k >> 3) << 3) + ((k & 4) >> 2);
            int swn = (n & 2) << 2;
            uint32_t* row = Bs[n];
            row[(base + 0) ^ swn] = f2tf(b4.x);
            row[(base + 2) ^ swn] = f2tf(b4.y);
            row[(base + 4) ^ swn] = f2tf(b4.z);
            row[(base + 6) ^ swn] = f2tf(b4.w);
        }
        __syncthreads();
        #pragma unroll
        for (int kk = 0; kk < BK2; kk += 8) {
            int col = (kk + 2 * tg) ^ sw;
            uint32_t af[4], bf[16][2];
            uint2 lo = *(const uint2*)&As[tm0 + g    ][col];
            uint2 hi = *(const uint2*)&As[tm0 + g + 8][col];
            af[0] = lo.x; af[1] = hi.x; af[2] = lo.y; af[3] = hi.y;
            #pragma unroll
            for (int j = 0; j < 16; j++) {
                uint2 bb = *(const uint2*)&Bs[tn0 + j * 8 + g][col];
                bf[j][0] = bb.x; bf[j][1] = bb.y;
            }
            #pragma unroll
            for (int j = 0; j < 16; j++)
                mma_tf32(acc[j][0], acc[j][1], acc[j][2], acc[j][3],
                         af[0], af[1], af[2], af[3], bf[j][0], bf[j][1]);
        }
        __syncthreads();
    }

    // fused softmax over the full 256-wide row
    float mx0 = -1e30f, mx1 = -1e30f;
    #pragma unroll
    for (int j = 0; j < 16; j++) {
        mx0 = fmaxf(mx0, fmaxf(acc[j][0], acc[j][1]));
        mx1 = fmaxf(mx1, fmaxf(acc[j][2], acc[j][3]));
    }
    mx0 = fmaxf(mx0, __shfl_xor_sync(0xffffffffu, mx0, 1));
    mx0 = fmaxf(mx0, __shfl_xor_sync(0xffffffffu, mx0, 2));
    mx1 = fmaxf(mx1, __shfl_xor_sync(0xffffffffu, mx1, 1));
    mx1 = fmaxf(mx1, __shfl_xor_sync(0xffffffffu, mx1, 2));
    if (tg == 0) { redM[wn][tm0 + g] = mx0; redM[wn][tm0 + g + 8] = mx1; }
    __syncthreads();
    mx0 = fmaxf(redM[0][tm0 + g],     redM[1][tm0 + g]);
    mx1 = fmaxf(redM[0][tm0 + g + 8], redM[1][tm0 + g + 8]);

    float s0 = 0.f, s1 = 0.f;
    #pragma unroll
    for (int j = 0; j < 16; j++) {
        float e0 = __expf(acc[j][0] - mx0);
        float e1 = __expf(acc[j][1] - mx0);
        float e2 = __expf(acc[j][2] - mx1);
        float e3 = __expf(acc[j][3] - mx1);
        acc[j][0] = e0; acc[j][1] = e1; acc[j][2] = e2; acc[j][3] = e3;
        s0 += e0 + e1; s1 += e2 + e3;
    }
    s0 += __shfl_xor_sync(0xffffffffu, s0, 1);
    s0 += __shfl_xor_sync(0xffffffffu, s0, 2);
    s1 += __shfl_xor_sync(0xffffffffu, s1, 1);
    s1 += __shfl_xor_sync(0xffffffffu, s1, 2);
    if (tg == 0) { redS[wn][tm0 + g] = s0; redS[wn][tm0 + g + 8] = s1; }
    __syncthreads();
    float i0 = 1.f / (redS[0][tm0 + g]     + redS[1][tm0 + g]);
    float i1 = 1.f / (redS[0][tm0 + g + 8] + redS[1][tm0 + g + 8]);

    int r0 = m0 + tm0 + g;
    int r1 = r0 + 8;
    #pragma unroll
    for (int j = 0; j < 16; j++) {
        int cc = tn0 + j * 8 + tg * 2;
        *(float2*)(Cb + (long long)r0 * 256 + cc) =
            make_float2(acc[j][0] * i0, acc[j][1] * i0);
        *(float2*)(Cb + (long long)r1 * 256 + cc) =
            make_float2(acc[j][2] * i1, acc[j][3] * i1);
    }
}

// ---------------- landmark means ---------------------------------------------
__global__ __launch_bounds__(256) void landmark_kernel()
{
    int id = blockIdx.x * 256 + threadIdx.x;
    const int half = BH_ * M_ * DH_;
    bool isK = id >= half;
    int t = isK ? id - half : id;
    int d  = t & 63;
    int m  = (t >> 6) & 255;
    int bh = t >> 14;
    const float* src = (isK ? g_k : g_q) + ((long long)bh * N_ + m * L_) * DH_ + d;
    float s = 0.f;
    #pragma unroll
    for (int l = 0; l < L_; l++) s += src[l * DH_];
    (isK ? g_kl : g_ql)[t] = s * (1.0f / L_);
}

// ---------------- exp-softmax pass for a3 (writes exp, saves row sums) -------
__global__ __launch_bounds__(256) void softmax_e_kernel(
    float* __restrict__ x, float* __restrict__ sums)
{
    __shared__ float sh[256];
    float* row = x + (long long)blockIdx.x * N_;
    int tid = threadIdx.x;
    float m = -1e30f;
    #pragma unroll
    for (int i = 0; i < 4; i++) {
        float4 v = *(float4*)(row + (i * 256 + tid) * 4);
        m = fmaxf(m, fmaxf(fmaxf(v.x, v.y), fmaxf(v.z, v.w)));
    }
    m = blockReduceMax(m, sh);
    float s = 0.f;
    #pragma unroll
    for (int i = 0; i < 4; i++) {
        float4 v = *(float4*)(row + (i * 256 + tid) * 4);
        v.x = __expf(v.x - m); v.y = __expf(v.y - m);
        v.z = __expf(v.z - m); v.w = __expf(v.w - m);
        *(float4*)(row + (i * 256 + tid) * 4) = v;
        s += v.x + v.y + v.z + v.w;
    }
    s = blockReduceSum(s, sh);
    if (tid == 0) sums[blockIdx.x] = s;
}

// ---------------- a3v split-K reduce + row normalize -------------------------
__global__ __launch_bounds__(256) void a3v_reduce_kernel()
{
    int idx = blockIdx.x * 256 + threadIdx.x;         // BH_*M_*DH_
    int rrow = idx >> 6;                              // bh*256+m
    int bh = idx >> 14;
    int inner = idx & 16383;
    long long base = (long long)bh * 4 * 16384 + inner;
    float s = g_part[base] + g_part[base + 16384]
            + g_part[base + 2 * 16384] + g_part[base + 3 * 16384];
    g_a3v[idx] = s / g_rsum[rrow];
}

// ---------------- pinv init ---------------------------------------------------
__global__ void zero_max_kernel() { g_max[0] = 0.f; g_max[1] = 0.f; }

__global__ __launch_bounds__(256) void pinv_absmax_kernel()
{
    __shared__ float sh[256];
    const float* X = g_a2 + (long long)blockIdx.x * (M_ * M_);
    int tid = threadIdx.x;
    float cs = 0.f, rs = 0.f;
    for (int j = 0; j < M_; j++) cs += fabsf(X[tid * M_ + j]);
    for (int i = 0; i < M_; i++) rs += fabsf(X[i * M_ + tid]);
    float cm = blockReduceMax(cs, sh);
    float rm = blockReduceMax(rs, sh);
    if (tid == 0) {
        atomicMax(reinterpret_cast<int*>(&g_max[0]), __float_as_int(cm));
        atomicMax(reinterpret_cast<int*>(&g_max[1]), __float_as_int(rm));
    }
}

__global__ __launch_bounds__(256) void zinit_kernel()
{
    long long id = (long long)blockIdx.x * 256 + threadIdx.x;
    float inv = 1.0f / (g_max[0] * g_max[1]);
    long long bh = id >> 16;
    int rem = (int)(id & 65535);
    int row = rem >> 8, col = rem & 255;
    g_z0[id] = g_a2[bh * (M_ * M_) + (long long)col * M_ + row] * inv;
}

// ---------------- depthwise conv residual added into ctx ----------------------
__global__ __launch_bounds__(256) void conv_add_kernel(const float* __restrict__ cw)
{
    long long id = (long long)blockIdx.x * 256 + threadIdx.x;  // BH_*N_*DH_
    int d = (int)(id & 63);
    int i = (int)((id >> 6) & 4095);
    int bh = (int)(id >> 18);
    int h = bh & 7, b = bh >> 3;
    const float* vb = g_v + ((long long)bh << 18);
    float acc = 0.f;
    #pragma unroll
    for (int k = 0; k < 33; k++) {
        int s = i + k - 16;
        if ((unsigned)s < (unsigned)N_) acc += cw[h * 33 + k] * vb[(long long)s * DH_ + d];
    }
    g_ctx[((long long)(b * N_ + i)) * DIM_ + h * DH_ + d] += acc;
}

// ---------------- host helpers -------------------------------------------------
static float* symaddr(const void* sym) {
    void* p = nullptr;
    cudaGetSymbolAddress(&p, sym);
    return (float*)p;
}

template<int MODE>
static void gemm(const float* A, const float* B, float* C,
                 int M, int N, int K, int batch, int ldA, int ldB,
                 long long sA, long long sB, long long sC, bool tb,
                 float alpha = 1.f,
                 const float* resid = nullptr, float rs = 0.f,
                 const float* rsPtr = nullptr,
                 const float* bias = nullptr,
                 bool forceBN64 = false)
{
    dim3 block(256);
    if (N % 128 == 0 && !forceBN64) {
        dim3 grid(N / 128, M / 128, batch);
        if (tb)
            mma_gemm_kernel<128, 128, true , MODE, false><<<grid, block>>>(
                A, B, C, N, K, ldA, ldB, sA, sB, sC, alpha, resid, rs, rsPtr, bias);
        else
            mma_gemm_kernel<128, 128, false, MODE, false><<<grid, block>>>(
                A, B, C, N, K, ldA, ldB, sA, sB, sC, alpha, resid, rs, rsPtr, bias);
    } else {
        dim3 grid(N / 64, M / 128, batch);
        if (tb)
            mma_gemm_kernel<128, 64, true , MODE, false><<<grid, block>>>(
                A, B, C, N, K, ldA, ldB, sA, sB, sC, alpha, resid, rs, rsPtr, bias);
        else
            mma_gemm_kernel<128, 64, false, MODE, false><<<grid, block>>>(
                A, B, C, N, K, ldA, ldB, sA, sB, sC, alpha, resid, rs, rsPtr, bias);
    }
}

extern "C" void kernel_launch(void* const* d_in, const int* in_sizes, int n_in,
                              void* d_out, int out_size)
{
    const float* x      = (const float*)d_in[0];
    const float* ln_w   = (const float*)d_in[1];
    const float* ln_b   = (const float*)d_in[2];
    const float* w_qkv  = (const float*)d_in[3];
    const float* w_out  = (const float*)d_in[4];
    const float* b_out  = (const float*)d_in[5];
    const float* conv_w = (const float*)d_in[6];
    const float* omega  = (const float*)d_in[7];
    float* out = (float*)d_out;

    float* p_ln   = symaddr(g_ln);
    float* p_q    = symaddr(g_q);
    float* p_k    = symaddr(g_k);
    float* p_v    = symaddr(g_v);
    float* p_ql   = symaddr(g_ql);
    float* p_kl   = symaddr(g_kl);
    float* p_a1   = symaddr(g_a1);
    float* p_a3   = symaddr(g_a3);
    float* p_a2   = symaddr(g_a2);
    float* p_z0   = symaddr(g_z0);
    float* p_z1   = symaddr(g_z1);
    float* p_t1   = symaddr(g_t1);
    float* p_t2   = symaddr(g_t2);
    float* p_t3   = symaddr(g_t3);
    float* p_a3v  = symaddr(g_a3v);
    float* p_part = symaddr(g_part);
    float* p_rsum = symaddr(g_rsum);
    float* p_ctx  = symaddr(g_ctx);

    const long long sQ  = (long long)N_ * DH_;     // 262144
    const long long sL  = (long long)M_ * DH_;     // 16384
    const long long sS1 = (long long)N_ * M_;      // 1048576
    const long long sA2 = (long long)M_ * M_;      // 65536

    // 1) layernorm
    ln_kernel<<<ROWS_, 256>>>(x, ln_w, ln_b);

    // 2) qkv projection, epilogue writes q (scaled), k, v head-major
    gemm<1>(p_ln, w_qkv, nullptr, ROWS_, 3 * DIM_, DIM_, 1, DIM_, 3 * DIM_,
            0, 0, 0, false);

    // 3) landmarks
    landmark_kernel<<<(2 * BH_ * M_ * DH_) / 256, 256>>>();

    // 4) sim1 + softmax -> a1 (normalized); sim2 + softmax -> a2
    {
        dim3 block(256);
        sim_softmax_kernel<<<dim3(1, N_ / 64, BH_), block>>>(
            p_q, p_kl, p_a1, DH_, sQ, sL, sS1);
        sim_softmax_kernel<<<dim3(1, M_ / 64, BH_), block>>>(
            p_ql, p_kl, p_a2, DH_, sL, sL, sA2);
    }

    // 5) sim3 -> a3, then exp pass with row sums
    gemm<0>(p_ql, p_k, p_a3, M_, N_, DH_, BH_, DH_, DH_, sL, sQ, sS1, true);
    softmax_e_kernel<<<BH_ * M_, 256>>>(p_a3, p_rsum);

    // 6) Moore-Penrose pinv of a2 (Newton-Schulz, 6 iters)
    zero_max_kernel<<<1, 1>>>();
    pinv_absmax_kernel<<<BH_, 256>>>();
    zinit_kernel<<<(BH_ * M_ * M_) / 256, 256>>>();

    for (int it = 0; it < 6; it++) {
        float* zin  = (it & 1) ? p_z1 : p_z0;
        float* zout = (it & 1) ? p_z0 : p_z1;
        gemm<0>(p_a2, zin, p_t1, M_, M_, M_, BH_, M_, M_, sA2, sA2, sA2, false,
                1.f, nullptr, 0.f, nullptr, nullptr, true);
        gemm<0>(p_t1, p_t1, p_t2, M_, M_, M_, BH_, M_, M_, sA2, sA2, sA2, false,
                -1.f, p_t1, 7.f, nullptr, nullptr, true);
        gemm<0>(p_t1, p_t2, p_t3, M_, M_, M_, BH_, M_, M_, sA2, sA2, sA2, false,
                -1.f, p_t1, 15.f, nullptr, nullptr, true);
        gemm<0>(zin, p_t3, zout, M_, M_, M_, BH_, M_, M_, sA2, sA2, sA2, false,
                -0.25f, zin, 3.25f, nullptr, nullptr, true);
    }

    // 7) a3v = (exp(sim3) @ v) / rowsum, split-K x4
    {
        dim3 grid(1, M_ / 128, BH_ * 4), block(256);
        mma_gemm_kernel<128, 64, false, 0, true><<<grid, block>>>(
            p_a3, p_v, p_part, DH_, N_ / 4, N_, DH_, sS1, sQ, sL,
            1.f, nullptr, 0.f, nullptr, nullptr);
        a3v_reduce_kernel<<<(BH_ * M_ * DH_) / 256, 256>>>();
    }

    // 8) a1 @ a2inv -> reuse g_a3 ([n, m])
    gemm<0>(p_a1, p_z0, p_a3, N_, M_, M_, BH_, M_, M_, sS1, sA2, sS1, false);

    // 9) (a1 a2inv) @ a3v -> ctx layout directly
    gemm<2>(p_a3, p_a3v, nullptr, N_, DH_, M_, BH_, M_, DH_, sS1, sL, 0, false);

    // 10) depthwise conv residual added into ctx
    conv_add_kernel<<<(BH_ * N_ * DH_) / 256, 256>>>(conv_w);

    // 11) output projection + bias + omega * x
    gemm<0>(p_ctx, w_out, out, ROWS_, DIM_, DIM_, 1, DIM_, DIM_, 0, 0, 0, false,
            1.f, x, 0.f, omega, b_out);
}

// round 5
// speedup vs baseline: 1.8381x; 1.8381x over previous
#include <cuda_runtime.h>
#include <cuda_bf16.h>
#include <cstdint>

// ---------------------------------------------------------------------------
// Nystrom attention transformer layer. TF32 mma GEMMs with cp.async pipeline
// and conflict-free stride-20 smem layout. Fused epilogues.
// ---------------------------------------------------------------------------

#define B_    4
#define N_    4096
#define DIM_  512
#define H_    8
#define DH_   64
#define M_    256
#define L_    16
#define ROWS_ (B_ * N_)          // 16384
#define BH_   (B_ * H_)          // 32

// ---------------- scratch (device globals) ----------------------------------
__device__ float g_ln  [ROWS_ * DIM_];
__device__ float g_q   [BH_ * N_ * DH_];
__device__ float g_k   [BH_ * N_ * DH_];
__device__ float g_v   [BH_ * N_ * DH_];
__device__ float g_ql  [BH_ * M_ * DH_];
__device__ float g_kl  [BH_ * M_ * DH_];
__device__ float g_a1  [BH_ * N_ * M_];
__device__ float g_a3  [BH_ * M_ * N_];     // sim3 exp; later reused for a1@a2inv
__device__ float g_a2  [BH_ * M_ * M_];
__device__ float g_z0  [BH_ * M_ * M_];
__device__ float g_z1  [BH_ * M_ * M_];
__device__ float g_t1  [BH_ * M_ * M_];
__device__ float g_t2  [BH_ * M_ * M_];
__device__ float g_t3  [BH_ * M_ * M_];
__device__ float g_a3v [BH_ * M_ * DH_];
__device__ float g_part[BH_ * 4 * M_ * DH_];
__device__ float g_rsum[BH_ * M_];
__device__ float g_ctx [ROWS_ * DIM_];
__device__ float g_max [2];

// ---------------- reductions -------------------------------------------------
__device__ __forceinline__ float blockReduceSum(float v, float* sh) {
    int tid = threadIdx.x;
    sh[tid] = v; __syncthreads();
    for (int s = 128; s > 0; s >>= 1) {
        if (tid < s) sh[tid] += sh[tid + s];
        __syncthreads();
    }
    float r = sh[0]; __syncthreads();
    return r;
}
__device__ __forceinline__ float blockReduceMax(float v, float* sh) {
    int tid = threadIdx.x;
    sh[tid] = v; __syncthreads();
    for (int s = 128; s > 0; s >>= 1) {
        if (tid < s) sh[tid] = fmaxf(sh[tid], sh[tid + s]);
        __syncthreads();
    }
    float r = sh[0]; __syncthreads();
    return r;
}

// ---------------- layernorm --------------------------------------------------
__global__ __launch_bounds__(256) void ln_kernel(
    const float* __restrict__ x, const float* __restrict__ w,
    const float* __restrict__ b)
{
    __shared__ float sh[256];
    long long r = blockIdx.x;
    const float* xr = x + r * DIM_;
    int tid = threadIdx.x;
    float v0 = xr[tid], v1 = xr[tid + 256];
    float s = blockReduceSum(v0 + v1, sh);
    float mu = s * (1.0f / DIM_);
    float d0 = v0 - mu, d1 = v1 - mu;
    float s2 = blockReduceSum(d0 * d0 + d1 * d1, sh);
    float inv = rsqrtf(s2 * (1.0f / DIM_) + 1e-5f);
    g_ln[r * DIM_ + tid]        = d0 * inv * w[tid] + b[tid];
    g_ln[r * DIM_ + tid + 256]  = d1 * inv * w[tid + 256] + b[tid + 256];
}

// ---------------- TF32 helpers ----------------------------------------------
__device__ __forceinline__ uint32_t f2tf(float f) {
    uint32_t r;
    asm("cvt.rna.tf32.f32 %0, %1;" : "=r"(r) : "f"(f));
    return r;
}
__device__ __forceinline__ void mma_tf32(
    float& c0, float& c1, float& c2, float& c3,
    uint32_t a0, uint32_t a1, uint32_t a2, uint32_t a3,
    uint32_t b0, uint32_t b1)
{
    asm volatile(
        "mma.sync.aligned.m16n8k8.row.col.f32.tf32.tf32.f32 "
        "{%0,%1,%2,%3}, {%4,%5,%6,%7}, {%8,%9}, {%0,%1,%2,%3};"
        : "+f"(c0), "+f"(c1), "+f"(c2), "+f"(c3)
        : "r"(a0), "r"(a1), "r"(a2), "r"(a3), "r"(b0), "r"(b1));
}

// ---------------- cp.async helpers -------------------------------------------
__device__ __forceinline__ void cpa16(void* dst, const void* src) {
    uint32_t d = (uint32_t)__cvta_generic_to_shared(dst);
    asm volatile("cp.async.cg.shared.global [%0], [%1], 16;" :: "r"(d), "l"(src));
}
__device__ __forceinline__ void cpa4(void* dst, const void* src) {
    uint32_t d = (uint32_t)__cvta_generic_to_shared(dst);
    asm volatile("cp.async.ca.shared.global [%0], [%1], 4;" :: "r"(d), "l"(src));
}
#define CP_COMMIT() asm volatile("cp.async.commit_group;" ::: "memory")
#define CP_WAIT1()  asm volatile("cp.async.wait_group 1;" ::: "memory")

// ---------------- main mma GEMM: cp.async pipelined, stride-20 smem ----------
// MODE 0: standard epilogue; MODE 1: qkv split; MODE 2: ctx layout.
// SPLITK: blockIdx.z = bh*4 + split, Kdim = chunk length.
#define BK2 16
#define RS  20      // smem row stride in words (80B, 16B aligned, conflict-free)

template<int BM, int BN, bool TB, int MODE, bool SPLITK>
__global__ __launch_bounds__(256) void mma_gemm_kernel(
    const float* __restrict__ A, const float* __restrict__ B,
    float* __restrict__ C, int Ndim, int Kdim, int ldA, int ldB,
    long long sA, long long sB, long long sC,
    float alpha,
    const float* __restrict__ resid, float residScale,
    const float* __restrict__ residScalePtr,
    const float* __restrict__ bias)
{
    constexpr int TM = BM / 4;
    constexpr int TN = BN / 2;
    constexpr int MT = TM / 16;
    constexpr int NT = TN / 8;
    constexpr int STAGES = (BM + BN > 192) ? 2 : 3;
    constexpr int CHA = BM / 64;            // 16B chunks per thread (A)
    constexpr int CHB = BN / 64;            // 16B chunks per thread (B, TB)
    constexpr int SCB = (BK2 * BN) / 256;   // scalars per thread (B, !TB)

    __shared__ __align__(16) float As[STAGES][BM * RS];
    __shared__ __align__(16) float Bs[STAGES][BN * RS];

    int bz = blockIdx.z;
    long long aOff, bOff, cOff;
    if (SPLITK) {
        int bz0 = bz >> 2, sp = bz & 3;
        aOff = (long long)bz0 * sA + (long long)sp * Kdim;
        bOff = (long long)bz0 * sB + (long long)sp * Kdim * ldB;
        cOff = (long long)bz * sC;
    } else {
        aOff = (long long)bz * sA;
        bOff = (long long)bz * sB;
        cOff = (long long)bz * sC;
    }
    const float* Ab = A + aOff;
    const float* Bb = B + bOff;
    float*       Cb = C + cOff;
    const float* Rb = resid ? resid + cOff : nullptr;

    int n0 = blockIdx.x * BN;
    int m0 = blockIdx.y * BM;
    int tid  = threadIdx.x;
    int wid  = tid >> 5;
    int lane = tid & 31;
    int wm = wid >> 1, wn = wid & 1;
    int tm0 = wm * TM, tn0 = wn * TN;
    int g  = lane >> 2;
    int tg = lane & 3;

    float acc[MT][NT][4];
    #pragma unroll
    for (int i = 0; i < MT; i++)
        #pragma unroll
        for (int j = 0; j < NT; j++)
            #pragma unroll
            for (int c = 0; c < 4; c++) acc[i][j][c] = 0.f;

    auto loadTile = [&](int t, int st) {
        int k0 = t * BK2;
        #pragma unroll
        for (int c = 0; c < CHA; c++) {
            int id = c * 256 + tid;
            int m = id >> 2, kq = (id & 3) * 4;
            cpa16(&As[st][m * RS + kq],
                  Ab + (long long)(m0 + m) * ldA + k0 + kq);
        }
        if (TB) {
            #pragma unroll
            for (int c = 0; c < CHB; c++) {
                int id = c * 256 + tid;
                int n = id >> 2, kq = (id & 3) * 4;
                cpa16(&Bs[st][n * RS + kq],
                      Bb + (long long)(n0 + n) * ldB + k0 + kq);
            }
        } else {
            int n  = tid & (BN - 1);
            int kt = (tid / BN) * SCB;
            #pragma unroll
            for (int c = 0; c < SCB; c++) {
                int k = kt + c;
                cpa4(&Bs[st][n * RS + k],
                     Bb + (long long)(k0 + k) * ldB + n0 + n);
            }
        }
    };

    auto computeStage = [&](int st) {
        const float* as = As[st];
        const float* bs = Bs[st];
        #pragma unroll
        for (int kk = 0; kk < BK2; kk += 8) {
            int c0 = kk + tg, c1 = c0 + 4;
            uint32_t af[MT][4], bf[NT][2];
            #pragma unroll
            for (int i = 0; i < MT; i++) {
                int r0 = (tm0 + i * 16 + g) * RS;
                int r1 = r0 + 8 * RS;
                af[i][0] = __float_as_uint(as[r0 + c0]);
                af[i][1] = __float_as_uint(as[r1 + c0]);
                af[i][2] = __float_as_uint(as[r0 + c1]);
                af[i][3] = __float_as_uint(as[r1 + c1]);
            }
            #pragma unroll
            for (int j = 0; j < NT; j++) {
                int rn = (tn0 + j * 8 + g) * RS;
                bf[j][0] = __float_as_uint(bs[rn + c0]);
                bf[j][1] = __float_as_uint(bs[rn + c1]);
            }
            #pragma unroll
            for (int i = 0; i < MT; i++)
                #pragma unroll
                for (int j = 0; j < NT; j++)
                    mma_tf32(acc[i][j][0], acc[i][j][1], acc[i][j][2], acc[i][j][3],
                             af[i][0], af[i][1], af[i][2], af[i][3],
                             bf[j][0], bf[j][1]);
        }
    };

    int nIter = Kdim / BK2;
    loadTile(0, 0); CP_COMMIT();
    loadTile(1, 1); CP_COMMIT();
    int p = 0;
    for (int t = 0; t < nIter; t++) {
        CP_WAIT1();
        __syncthreads();
        computeStage(p);
        if (STAGES == 2) __syncthreads();
        if (t + 2 < nIter) {
            int st = p + 2;
            if (st >= STAGES) st -= STAGES;
            loadTile(t + 2, st);
        }
        CP_COMMIT();
        p = (p + 1 == STAGES) ? 0 : p + 1;
    }

    // ---------------- epilogue ----------------
    float rs = residScalePtr ? *residScalePtr : residScale;
    #pragma unroll
    for (int i = 0; i < MT; i++) {
        int r0 = m0 + tm0 + i * 16 + g;
        int r1 = r0 + 8;
        #pragma unroll
        for (int j = 0; j < NT; j++) {
            int cc = n0 + tn0 + j * 8 + tg * 2;
            if (MODE == 0) {
                float2 bv = bias ? *(const float2*)(bias + cc) : make_float2(0.f, 0.f);
                float2 v0 = make_float2(alpha * acc[i][j][0] + bv.x,
                                        alpha * acc[i][j][1] + bv.y);
                float2 v1 = make_float2(alpha * acc[i][j][2] + bv.x,
                                        alpha * acc[i][j][3] + bv.y);
                if (Rb) {
                    float2 q0 = *(const float2*)(Rb + (long long)r0 * Ndim + cc);
                    float2 q1 = *(const float2*)(Rb + (long long)r1 * Ndim + cc);
                    v0.x += rs * q0.x; v0.y += rs * q0.y;
                    v1.x += rs * q1.x; v1.y += rs * q1.y;
                }
                *(float2*)(Cb + (long long)r0 * Ndim + cc) = v0;
                *(float2*)(Cb + (long long)r1 * Ndim + cc) = v1;
            } else if (MODE == 1) {
                int which = cc >> 9;
                int hc = cc & 511;
                int h = hc >> 6, d = hc & 63;
                float sc = (which == 0) ? 0.125f : 1.0f;
                float* dstbuf = (which == 0) ? g_q : (which == 1) ? g_k : g_v;
                #pragma unroll
                for (int rr = 0; rr < 2; rr++) {
                    int row = rr ? r1 : r0;
                    int b = row >> 12, nn = row & 4095;
                    long long dst = (((long long)((b << 3) + h)) * N_ + nn) * DH_ + d;
                    float2 v = rr ? make_float2(sc * acc[i][j][2], sc * acc[i][j][3])
                                  : make_float2(sc * acc[i][j][0], sc * acc[i][j][1]);
                    *(float2*)(dstbuf + dst) = v;
                }
            } else {
                int b = bz >> 3, h = bz & 7;
                *(float2*)(g_ctx + ((long long)(b * N_ + r0)) * DIM_ + h * DH_ + cc) =
                    make_float2(acc[i][j][0], acc[i][j][1]);
                *(float2*)(g_ctx + ((long long)(b * N_ + r1)) * DIM_ + h * DH_ + cc) =
                    make_float2(acc[i][j][2], acc[i][j][3]);
            }
        }
    }
}

// ---------------- sim GEMM (TB) with fused full-row softmax ------------------
// (unchanged from round 3 — known-good)
__global__ __launch_bounds__(256) void sim_softmax_kernel(
    const float* __restrict__ A, const float* __restrict__ Bm,
    float* __restrict__ C, int Kdim,
    long long sA, long long sB, long long sC)
{
    constexpr int BMs = 64, BNs = 256, BKs = 32;
    __shared__ uint32_t As[BKs][BMs + 5];
    __shared__ uint32_t Bs[BKs][BNs + 5];
    __shared__ float redM[2][BMs];
    __shared__ float redS[2][BMs];

    int bz = blockIdx.z;
    const float* Ab = A + (long long)bz * sA;
    const float* Bb = Bm + (long long)bz * sB;
    float*       Cb = C + (long long)bz * sC;

    int m0 = blockIdx.y * BMs;
    int tid  = threadIdx.x;
    int wid  = tid >> 5;
    int lane = tid & 31;
    int wm = wid >> 1, wn = wid & 1;
    int tm0 = wm * 16, tn0 = wn * 128;
    int g  = lane >> 2;
    int tg = lane & 3;

    float acc[16][4];
    #pragma unroll
    for (int j = 0; j < 16; j++)
        #pragma unroll
        for (int c = 0; c < 4; c++) acc[j][c] = 0.f;

    for (int k0 = 0; k0 < Kdim; k0 += BKs) {
        {
            #pragma unroll
            for (int c = 0; c < 2; c++) {
                int e = (c * 256 + tid) * 4;
                int m = e >> 5, k = e & 31;
                float4 a4 = *(const float4*)(Ab + (long long)(m0 + m) * Kdim + k0 + k);
                As[k + 0][m] = f2tf(a4.x); As[k + 1][m] = f2tf(a4.y);
                As[k + 2][m] = f2tf(a4.z); As[k + 3][m] = f2tf(a4.w);
            }
            #pragma unroll
            for (int c = 0; c < 8; c++) {
                int e = (c * 256 + tid) * 4;
                int k = e & 31, n = e >> 5;
                float4 b4 = *(const float4*)(Bb + (long long)n * Kdim + k0 + k);
                Bs[k + 0][n] = f2tf(b4.x); Bs[k + 1][n] = f2tf(b4.y);
                Bs[k + 2][n] = f2tf(b4.z); Bs[k + 3][n] = f2tf(b4.w);
            }
        }
        __syncthreads();
        #pragma unroll
        for (int kk = 0; kk < BKs; kk += 8) {
            uint32_t af[4], bf[16][2];
            af[0] = As[kk + tg    ][tm0 + g    ];
            af[1] = As[kk + tg    ][tm0 + g + 8];
            af[2] = As[kk + tg + 4][tm0 + g    ];
            af[3] = As[kk + tg + 4][tm0 + g + 8];
            #pragma unroll
            for (int j = 0; j < 16; j++) {
                int nb = tn0 + j * 8;
                bf[j][0] = Bs[kk + tg    ][nb + g];
                bf[j][1] = Bs[kk + tg + 4][nb + g];
            }
            #pragma unroll
            for (int j = 0; j < 16; j++)
                mma_tf32(acc[j][0], acc[j][1], acc[j][2], acc[j][3],
                         af[0], af[1], af[2], af[3], bf[j][0], bf[j][1]);
        }
        __syncthreads();
    }

    float mx0 = -1e30f, mx1 = -1e30f;
    #pragma unroll
    for (int j = 0; j < 16; j++) {
        mx0 = fmaxf(mx0, fmaxf(acc[j][0], acc[j][1]));
        mx1 = fmaxf(mx1, fmaxf(acc[j][2], acc[j][3]));
    }
    mx0 = fmaxf(mx0, __shfl_xor_sync(0xffffffffu, mx0, 1));
    mx0 = fmaxf(mx0, __shfl_xor_sync(0xffffffffu, mx0, 2));
    mx1 = fmaxf(mx1, __shfl_xor_sync(0xffffffffu, mx1, 1));
    mx1 = fmaxf(mx1, __shfl_xor_sync(0xffffffffu, mx1, 2));
    if (tg == 0) { redM[wn][tm0 + g] = mx0; redM[wn][tm0 + g + 8] = mx1; }
    __syncthreads();
    mx0 = fmaxf(redM[0][tm0 + g],     redM[1][tm0 + g]);
    mx1 = fmaxf(redM[0][tm0 + g + 8], redM[1][tm0 + g + 8]);

    float s0 = 0.f, s1 = 0.f;
    #pragma unroll
    for (int j = 0; j < 16; j++) {
        float e0 = __expf(acc[j][0] - mx0);
        float e1 = __expf(acc[j][1] - mx0);
        float e2 = __expf(acc[j][2] - mx1);
        float e3 = __expf(acc[j][3] - mx1);
        acc[j][0] = e0; acc[j][1] = e1; acc[j][2] = e2; acc[j][3] = e3;
        s0 += e0 + e1; s1 += e2 + e3;
    }
    s0 += __shfl_xor_sync(0xffffffffu, s0, 1);
    s0 += __shfl_xor_sync(0xffffffffu, s0, 2);
    s1 += __shfl_xor_sync(0xffffffffu, s1, 1);
    s1 += __shfl_xor_sync(0xffffffffu, s1, 2);
    if (tg == 0) { redS[wn][tm0 + g] = s0; redS[wn][tm0 + g + 8] = s1; }
    __syncthreads();
    float i0 = 1.f / (redS[0][tm0 + g]     + redS[1][tm0 + g]);
    float i1 = 1.f / (redS[0][tm0 + g + 8] + redS[1][tm0 + g + 8]);

    int r0 = m0 + tm0 + g;
    int r1 = r0 + 8;
    #pragma unroll
    for (int j = 0; j < 16; j++) {
        int cc = tn0 + j * 8 + tg * 2;
        *(float2*)(Cb + (long long)r0 * 256 + cc) =
            make_float2(acc[j][0] * i0, acc[j][1] * i0);
        *(float2*)(Cb + (long long)r1 * 256 + cc) =
            make_float2(acc[j][2] * i1, acc[j][3] * i1);
    }
}

// ---------------- landmark means ---------------------------------------------
__global__ __launch_bounds__(256) void landmark_kernel()
{
    int id = blockIdx.x * 256 + threadIdx.x;
    const int half = BH_ * M_ * DH_;
    bool isK = id >= half;
    int t = isK ? id - half : id;
    int d  = t & 63;
    int m  = (t >> 6) & 255;
    int bh = t >> 14;
    const float* src = (isK ? g_k : g_q) + ((long long)bh * N_ + m * L_) * DH_ + d;
    float s = 0.f;
    #pragma unroll
    for (int l = 0; l < L_; l++) s += src[l * DH_];
    (isK ? g_kl : g_ql)[t] = s * (1.0f / L_);
}

// ---------------- exp-softmax pass for a3 (writes exp, saves row sums) -------
__global__ __launch_bounds__(256) void softmax_e_kernel(
    float* __restrict__ x, float* __restrict__ sums)
{
    __shared__ float sh[256];
    float* row = x + (long long)blockIdx.x * N_;
    int tid = threadIdx.x;
    float m = -1e30f;
    #pragma unroll
    for (int i = 0; i < 4; i++) {
        float4 v = *(float4*)(row + (i * 256 + tid) * 4);
        m = fmaxf(m, fmaxf(fmaxf(v.x, v.y), fmaxf(v.z, v.w)));
    }
    m = blockReduceMax(m, sh);
    float s = 0.f;
    #pragma unroll
    for (int i = 0; i < 4; i++) {
        float4 v = *(float4*)(row + (i * 256 + tid) * 4);
        v.x = __expf(v.x - m); v.y = __expf(v.y - m);
        v.z = __expf(v.z - m); v.w = __expf(v.w - m);
        *(float4*)(row + (i * 256 + tid) * 4) = v;
        s += v.x + v.y + v.z + v.w;
    }
    s = blockReduceSum(s, sh);
    if (tid == 0) sums[blockIdx.x] = s;
}

// ---------------- a3v split-K reduce + row normalize -------------------------
__global__ __launch_bounds__(256) void a3v_reduce_kernel()
{
    int idx = blockIdx.x * 256 + threadIdx.x;         // BH_*M_*DH_
    int rrow = idx >> 6;                              // bh*256+m
    int bh = idx >> 14;
    int inner = idx & 16383;
    long long base = (long long)bh * 4 * 16384 + inner;
    float s = g_part[base] + g_part[base + 16384]
            + g_part[base + 2 * 16384] + g_part[base + 3 * 16384];
    g_a3v[idx] = s / g_rsum[rrow];
}

// ---------------- pinv init ---------------------------------------------------
__global__ void zero_max_kernel() { g_max[0] = 0.f; g_max[1] = 0.f; }

__global__ __launch_bounds__(256) void pinv_absmax_kernel()
{
    __shared__ float sh[256];
    const float* X = g_a2 + (long long)blockIdx.x * (M_ * M_);
    int tid = threadIdx.x;
    float cs = 0.f, rs = 0.f;
    for (int j = 0; j < M_; j++) cs += fabsf(X[tid * M_ + j]);
    for (int i = 0; i < M_; i++) rs += fabsf(X[i * M_ + tid]);
    float cm = blockReduceMax(cs, sh);
    float rm = blockReduceMax(rs, sh);
    if (tid == 0) {
        atomicMax(reinterpret_cast<int*>(&g_max[0]), __float_as_int(cm));
        atomicMax(reinterpret_cast<int*>(&g_max[1]), __float_as_int(rm));
    }
}

__global__ __launch_bounds__(256) void zinit_kernel()
{
    long long id = (long long)blockIdx.x * 256 + threadIdx.x;
    float inv = 1.0f / (g_max[0] * g_max[1]);
    long long bh = id >> 16;
    int rem = (int)(id & 65535);
    int row = rem >> 8, col = rem & 255;
    g_z0[id] = g_a2[bh * (M_ * M_) + (long long)col * M_ + row] * inv;
}

// ---------------- depthwise conv residual added into ctx ----------------------
__global__ __launch_bounds__(256) void conv_add_kernel(const float* __restrict__ cw)
{
    long long id = (long long)blockIdx.x * 256 + threadIdx.x;  // BH_*N_*DH_
    int d = (int)(id & 63);
    int i = (int)((id >> 6) & 4095);
    int bh = (int)(id >> 18);
    int h = bh & 7, b = bh >> 3;
    const float* vb = g_v + ((long long)bh << 18);
    float acc = 0.f;
    #pragma unroll
    for (int k = 0; k < 33; k++) {
        int s = i + k - 16;
        if ((unsigned)s < (unsigned)N_) acc += cw[h * 33 + k] * vb[(long long)s * DH_ + d];
    }
    g_ctx[((long long)(b * N_ + i)) * DIM_ + h * DH_ + d] += acc;
}

// ---------------- host helpers -------------------------------------------------
static float* symaddr(const void* sym) {
    void* p = nullptr;
    cudaGetSymbolAddress(&p, sym);
    return (float*)p;
}

template<int MODE>
static void gemm(const float* A, const float* B, float* C,
                 int M, int N, int K, int batch, int ldA, int ldB,
                 long long sA, long long sB, long long sC, bool tb,
                 float alpha = 1.f,
                 const float* resid = nullptr, float rs = 0.f,
                 const float* rsPtr = nullptr,
                 const float* bias = nullptr,
                 bool forceBN64 = false)
{
    dim3 block(256);
    if (N % 128 == 0 && !forceBN64) {
        dim3 grid(N / 128, M / 128, batch);
        if (tb)
            mma_gemm_kernel<128, 128, true , MODE, false><<<grid, block>>>(
                A, B, C, N, K, ldA, ldB, sA, sB, sC, alpha, resid, rs, rsPtr, bias);
        else
            mma_gemm_kernel<128, 128, false, MODE, false><<<grid, block>>>(
                A, B, C, N, K, ldA, ldB, sA, sB, sC, alpha, resid, rs, rsPtr, bias);
    } else {
        dim3 grid(N / 64, M / 128, batch);
        if (tb)
            mma_gemm_kernel<128, 64, true , MODE, false><<<grid, block>>>(
                A, B, C, N, K, ldA, ldB, sA, sB, sC, alpha, resid, rs, rsPtr, bias);
        else
            mma_gemm_kernel<128, 64, false, MODE, false><<<grid, block>>>(
                A, B, C, N, K, ldA, ldB, sA, sB, sC, alpha, resid, rs, rsPtr, bias);
    }
}

extern "C" void kernel_launch(void* const* d_in, const int* in_sizes, int n_in,
                              void* d_out, int out_size)
{
    const float* x      = (const float*)d_in[0];
    const float* ln_w   = (const float*)d_in[1];
    const float* ln_b   = (const float*)d_in[2];
    const float* w_qkv  = (const float*)d_in[3];
    const float* w_out  = (const float*)d_in[4];
    const float* b_out  = (const float*)d_in[5];
    const float* conv_w = (const float*)d_in[6];
    const float* omega  = (const float*)d_in[7];
    float* out = (float*)d_out;

    float* p_ln   = symaddr(g_ln);
    float* p_q    = symaddr(g_q);
    float* p_k    = symaddr(g_k);
    float* p_v    = symaddr(g_v);
    float* p_ql   = symaddr(g_ql);
    float* p_kl   = symaddr(g_kl);
    float* p_a1   = symaddr(g_a1);
    float* p_a3   = symaddr(g_a3);
    float* p_a2   = symaddr(g_a2);
    float* p_z0   = symaddr(g_z0);
    float* p_z1   = symaddr(g_z1);
    float* p_t1   = symaddr(g_t1);
    float* p_t2   = symaddr(g_t2);
    float* p_t3   = symaddr(g_t3);
    float* p_a3v  = symaddr(g_a3v);
    float* p_part = symaddr(g_part);
    float* p_rsum = symaddr(g_rsum);
    float* p_ctx  = symaddr(g_ctx);

    const long long sQ  = (long long)N_ * DH_;     // 262144
    const long long sL  = (long long)M_ * DH_;     // 16384
    const long long sS1 = (long long)N_ * M_;      // 1048576
    const long long sA2 = (long long)M_ * M_;      // 65536

    // 1) layernorm
    ln_kernel<<<ROWS_, 256>>>(x, ln_w, ln_b);

    // 2) qkv projection, epilogue writes q (scaled), k, v head-major
    gemm<1>(p_ln, w_qkv, nullptr, ROWS_, 3 * DIM_, DIM_, 1, DIM_, 3 * DIM_,
            0, 0, 0, false);

    // 3) landmarks
    landmark_kernel<<<(2 * BH_ * M_ * DH_) / 256, 256>>>();

    // 4) sim1 + softmax -> a1 (normalized); sim2 + softmax -> a2
    {
        dim3 block(256);
        sim_softmax_kernel<<<dim3(1, N_ / 64, BH_), block>>>(
            p_q, p_kl, p_a1, DH_, sQ, sL, sS1);
        sim_softmax_kernel<<<dim3(1, M_ / 64, BH_), block>>>(
            p_ql, p_kl, p_a2, DH_, sL, sL, sA2);
    }

    // 5) sim3 -> a3, then exp pass with row sums
    gemm<0>(p_ql, p_k, p_a3, M_, N_, DH_, BH_, DH_, DH_, sL, sQ, sS1, true);
    softmax_e_kernel<<<BH_ * M_, 256>>>(p_a3, p_rsum);

    // 6) Moore-Penrose pinv of a2 (Newton-Schulz, 6 iters)
    zero_max_kernel<<<1, 1>>>();
    pinv_absmax_kernel<<<BH_, 256>>>();
    zinit_kernel<<<(BH_ * M_ * M_) / 256, 256>>>();

    for (int it = 0; it < 6; it++) {
        float* zin  = (it & 1) ? p_z1 : p_z0;
        float* zout = (it & 1) ? p_z0 : p_z1;
        gemm<0>(p_a2, zin, p_t1, M_, M_, M_, BH_, M_, M_, sA2, sA2, sA2, false,
                1.f, nullptr, 0.f, nullptr, nullptr, true);
        gemm<0>(p_t1, p_t1, p_t2, M_, M_, M_, BH_, M_, M_, sA2, sA2, sA2, false,
                -1.f, p_t1, 7.f, nullptr, nullptr, true);
        gemm<0>(p_t1, p_t2, p_t3, M_, M_, M_, BH_, M_, M_, sA2, sA2, sA2, false,
                -1.f, p_t1, 15.f, nullptr, nullptr, true);
        gemm<0>(zin, p_t3, zout, M_, M_, M_, BH_, M_, M_, sA2, sA2, sA2, false,
                -0.25f, zin, 3.25f, nullptr, nullptr, true);
    }

    // 7) a3v = (exp(sim3) @ v) / rowsum, split-K x4
    {
        dim3 grid(1, M_ / 128, BH_ * 4), block(256);
        mma_gemm_kernel<128, 64, false, 0, true><<<grid, block>>>(
            p_a3, p_v, p_part, DH_, N_ / 4, N_, DH_, sS1, sQ, sL,
            1.f, nullptr, 0.f, nullptr, nullptr);
        a3v_reduce_kernel<<<(BH_ * M_ * DH_) / 256, 256>>>();
    }

    // 8) a1 @ a2inv -> reuse g_a3 ([n, m])
    gemm<0>(p_a1, p_z0, p_a3, N_, M_, M_, BH_, M_, M_, sS1, sA2, sS1, false);

    // 9) (a1 a2inv) @ a3v -> ctx layout directly
    gemm<2>(p_a3, p_a3v, nullptr, N_, DH_, M_, BH_, M_, DH_, sS1, sL, 0, false);

    // 10) depthwise conv residual added into ctx
    conv_add_kernel<<<(BH_ * N_ * DH_) / 256, 256>>>(conv_w);

    // 11) output projection + bias + omega * x
    gemm<0>(p_ctx, w_out, out, ROWS_, DIM_, DIM_, 1, DIM_, DIM_, 0, 0, 0, false,
            1.f, x, 0.f, omega, b_out);
}

// round 6
// speedup vs baseline: 2.2423x; 1.2199x over previous
#include <cuda_runtime.h>
#include <cuda_bf16.h>
#include <cstdint>

// ---------------------------------------------------------------------------
// Nystrom attention transformer layer. TF32 mma GEMMs, 64x64 warp tiles,
// cp.async, conflict-free smem layouts (stride-20 [row][k], stride-(BN+8) [k][n]).
// ---------------------------------------------------------------------------

#define B_    4
#define N_    4096
#define DIM_  512
#define H_    8
#define DH_   64
#define M_    256
#define L_    16
#define ROWS_ (B_ * N_)          // 16384
#define BH_   (B_ * H_)          // 32

// ---------------- scratch (device globals) ----------------------------------
__device__ float g_ln  [ROWS_ * DIM_];
__device__ float g_q   [BH_ * N_ * DH_];
__device__ float g_k   [BH_ * N_ * DH_];
__device__ float g_v   [BH_ * N_ * DH_];
__device__ float g_ql  [BH_ * M_ * DH_];
__device__ float g_kl  [BH_ * M_ * DH_];
__device__ float g_a1  [BH_ * N_ * M_];
__device__ float g_a3  [BH_ * M_ * N_];
__device__ float g_a2  [BH_ * M_ * M_];
__device__ float g_z0  [BH_ * M_ * M_];
__device__ float g_z1  [BH_ * M_ * M_];
__device__ float g_t1  [BH_ * M_ * M_];
__device__ float g_t2  [BH_ * M_ * M_];
__device__ float g_t3  [BH_ * M_ * M_];
__device__ float g_a3v [BH_ * M_ * DH_];
__device__ float g_part[BH_ * 4 * M_ * DH_];
__device__ float g_rsum[BH_ * M_];
__device__ float g_ctx [ROWS_ * DIM_];
__device__ float g_max [2];

// ---------------- reductions -------------------------------------------------
__device__ __forceinline__ float blockReduceSum(float v, float* sh) {
    int tid = threadIdx.x;
    sh[tid] = v; __syncthreads();
    for (int s = 128; s > 0; s >>= 1) {
        if (tid < s) sh[tid] += sh[tid + s];
        __syncthreads();
    }
    float r = sh[0]; __syncthreads();
    return r;
}
__device__ __forceinline__ float blockReduceMax(float v, float* sh) {
    int tid = threadIdx.x;
    sh[tid] = v; __syncthreads();
    for (int s = 128; s > 0; s >>= 1) {
        if (tid < s) sh[tid] = fmaxf(sh[tid], sh[tid + s]);
        __syncthreads();
    }
    float r = sh[0]; __syncthreads();
    return r;
}

// ---------------- layernorm --------------------------------------------------
__global__ __launch_bounds__(256) void ln_kernel(
    const float* __restrict__ x, const float* __restrict__ w,
    const float* __restrict__ b)
{
    __shared__ float sh[256];
    long long r = blockIdx.x;
    const float* xr = x + r * DIM_;
    int tid = threadIdx.x;
    float v0 = xr[tid], v1 = xr[tid + 256];
    float s = blockReduceSum(v0 + v1, sh);
    float mu = s * (1.0f / DIM_);
    float d0 = v0 - mu, d1 = v1 - mu;
    float s2 = blockReduceSum(d0 * d0 + d1 * d1, sh);
    float inv = rsqrtf(s2 * (1.0f / DIM_) + 1e-5f);
    g_ln[r * DIM_ + tid]        = d0 * inv * w[tid] + b[tid];
    g_ln[r * DIM_ + tid + 256]  = d1 * inv * w[tid + 256] + b[tid + 256];
}

// ---------------- mma + cp.async helpers -------------------------------------
__device__ __forceinline__ void mma_tf32(
    float& c0, float& c1, float& c2, float& c3,
    uint32_t a0, uint32_t a1, uint32_t a2, uint32_t a3,
    uint32_t b0, uint32_t b1)
{
    asm volatile(
        "mma.sync.aligned.m16n8k8.row.col.f32.tf32.tf32.f32 "
        "{%0,%1,%2,%3}, {%4,%5,%6,%7}, {%8,%9}, {%0,%1,%2,%3};"
        : "+f"(c0), "+f"(c1), "+f"(c2), "+f"(c3)
        : "r"(a0), "r"(a1), "r"(a2), "r"(a3), "r"(b0), "r"(b1));
}
__device__ __forceinline__ void cpa16(void* dst, const void* src) {
    uint32_t d = (uint32_t)__cvta_generic_to_shared(dst);
    asm volatile("cp.async.cg.shared.global [%0], [%1], 16;" :: "r"(d), "l"(src));
}
#define CP_COMMIT() asm volatile("cp.async.commit_group;" ::: "memory")
#define CP_WAIT1()  asm volatile("cp.async.wait_group 1;" ::: "memory")
#define CP_WAIT0()  asm volatile("cp.async.wait_group 0;" ::: "memory")

#define BK2 16
#define RS  20      // [row][k] stride (words): frag banks 20g+tg = all 32 distinct

// ---------------- main mma GEMM: 128 threads, 2x2 warps, 64x64 warp tile -----
// MODE 0: standard epilogue; MODE 1: qkv split; MODE 2: ctx layout.
// SPLITK: blockIdx.z = bh*4 + split, Kdim = chunk length.
template<int BM, int BN, bool TB, int MODE, bool SPLITK>
__global__ __launch_bounds__(128, 2) void mma_gemm_kernel(
    const float* __restrict__ A, const float* __restrict__ B,
    float* __restrict__ C, int Ndim, int Kdim, int ldA, int ldB,
    long long sA, long long sB, long long sC,
    float alpha,
    const float* __restrict__ resid, float residScale,
    const float* __restrict__ residScalePtr,
    const float* __restrict__ bias)
{
    constexpr int MT = 4;               // 64 rows / 16
    constexpr int NT = BN / 16;         // (BN/2) / 8
    constexpr int RSB = BN + 8;         // [k][n] stride: frag banks 8tg+g distinct
    constexpr int ASZ = BM * RS;
    constexpr int BSZ = TB ? BN * RS : BK2 * RSB;

    __shared__ __align__(16) float As[2][ASZ];
    __shared__ __align__(16) float Bs[2][BSZ];

    int bz = blockIdx.z;
    long long aOff, bOff, cOff;
    if (SPLITK) {
        int bz0 = bz >> 2, sp = bz & 3;
        aOff = (long long)bz0 * sA + (long long)sp * Kdim;
        bOff = (long long)bz0 * sB + (long long)sp * Kdim * ldB;
        cOff = (long long)bz * sC;
    } else {
        aOff = (long long)bz * sA;
        bOff = (long long)bz * sB;
        cOff = (long long)bz * sC;
    }
    const float* Ab = A + aOff;
    const float* Bb = B + bOff;
    float*       Cb = C + cOff;
    const float* Rb = resid ? resid + cOff : nullptr;

    int n0 = blockIdx.x * BN;
    int m0 = blockIdx.y * BM;
    int tid  = threadIdx.x;
    int wid  = tid >> 5;
    int lane = tid & 31;
    int wm = wid >> 1, wn = wid & 1;
    int tm0 = wm * 64, tn0 = wn * (BN / 2);
    int g  = lane >> 2;
    int tg = lane & 3;

    float acc[MT][NT][4];
    #pragma unroll
    for (int i = 0; i < MT; i++)
        #pragma unroll
        for (int j = 0; j < NT; j++)
            #pragma unroll
            for (int c = 0; c < 4; c++) acc[i][j][c] = 0.f;

    auto loadTile = [&](int t, int st) {
        int k0 = t * BK2;
        #pragma unroll
        for (int c = 0; c < BM / 32; c++) {
            int id = c * 128 + tid;
            int m = id >> 2, kq = (id & 3) * 4;
            cpa16(&As[st][m * RS + kq],
                  Ab + (long long)(m0 + m) * ldA + k0 + kq);
        }
        if (TB) {
            #pragma unroll
            for (int c = 0; c < BN / 32; c++) {
                int id = c * 128 + tid;
                int n = id >> 2, kq = (id & 3) * 4;
                cpa16(&Bs[st][n * RS + kq],
                      Bb + (long long)(n0 + n) * ldB + k0 + kq);
            }
        } else {
            constexpr int CPR = BN / 4;   // 16B chunks per k-row
            #pragma unroll
            for (int c = 0; c < BN / 32; c++) {
                int id = c * 128 + tid;
                int k = id / CPR, nq = (id % CPR) * 4;
                cpa16(&Bs[st][k * RSB + nq],
                      Bb + (long long)(k0 + k) * ldB + n0 + nq);
            }
        }
    };

    auto computeStage = [&](int st) {
        const float* as = As[st];
        const float* bs = Bs[st];
        #pragma unroll
        for (int kk = 0; kk < BK2; kk += 8) {
            int c0 = kk + tg, c1 = c0 + 4;
            uint32_t af[MT][4], bf[NT][2];
            #pragma unroll
            for (int i = 0; i < MT; i++) {
                int r0 = (tm0 + i * 16 + g) * RS;
                int r1 = r0 + 8 * RS;
                af[i][0] = __float_as_uint(as[r0 + c0]);
                af[i][1] = __float_as_uint(as[r1 + c0]);
                af[i][2] = __float_as_uint(as[r0 + c1]);
                af[i][3] = __float_as_uint(as[r1 + c1]);
            }
            #pragma unroll
            for (int j = 0; j < NT; j++) {
                if (TB) {
                    int rn = (tn0 + j * 8 + g) * RS;
                    bf[j][0] = __float_as_uint(bs[rn + c0]);
                    bf[j][1] = __float_as_uint(bs[rn + c1]);
                } else {
                    int b0 = c0 * RSB + tn0 + j * 8 + g;
                    bf[j][0] = __float_as_uint(bs[b0]);
                    bf[j][1] = __float_as_uint(bs[b0 + 4 * RSB]);
                }
            }
            #pragma unroll
            for (int i = 0; i < MT; i++)
                #pragma unroll
                for (int j = 0; j < NT; j++)
                    mma_tf32(acc[i][j][0], acc[i][j][1], acc[i][j][2], acc[i][j][3],
                             af[i][0], af[i][1], af[i][2], af[i][3],
                             bf[j][0], bf[j][1]);
        }
    };

    int nIter = Kdim / BK2;
    loadTile(0, 0); CP_COMMIT();
    loadTile(1, 1); CP_COMMIT();
    int p = 0;
    for (int t = 0; t < nIter; t++) {
        CP_WAIT1();
        __syncthreads();
        computeStage(p);
        __syncthreads();
        if (t + 2 < nIter) loadTile(t + 2, p);
        CP_COMMIT();
        p ^= 1;
    }

    // ---------------- epilogue ----------------
    float rs = residScalePtr ? *residScalePtr : residScale;
    #pragma unroll
    for (int i = 0; i < MT; i++) {
        int r0 = m0 + tm0 + i * 16 + g;
        int r1 = r0 + 8;
        #pragma unroll
        for (int j = 0; j < NT; j++) {
            int cc = n0 + tn0 + j * 8 + tg * 2;
            if (MODE == 0) {
                float2 bv = bias ? *(const float2*)(bias + cc) : make_float2(0.f, 0.f);
                float2 v0 = make_float2(alpha * acc[i][j][0] + bv.x,
                                        alpha * acc[i][j][1] + bv.y);
                float2 v1 = make_float2(alpha * acc[i][j][2] + bv.x,
                                        alpha * acc[i][j][3] + bv.y);
                if (Rb) {
                    float2 q0 = *(const float2*)(Rb + (long long)r0 * Ndim + cc);
                    float2 q1 = *(const float2*)(Rb + (long long)r1 * Ndim + cc);
                    v0.x += rs * q0.x; v0.y += rs * q0.y;
                    v1.x += rs * q1.x; v1.y += rs * q1.y;
                }
                *(float2*)(Cb + (long long)r0 * Ndim + cc) = v0;
                *(float2*)(Cb + (long long)r1 * Ndim + cc) = v1;
            } else if (MODE == 1) {
                int which = cc >> 9;
                int hc = cc & 511;
                int h = hc >> 6, d = hc & 63;
                float sc = (which == 0) ? 0.125f : 1.0f;
                float* dstbuf = (which == 0) ? g_q : (which == 1) ? g_k : g_v;
                #pragma unroll
                for (int rr = 0; rr < 2; rr++) {
                    int row = rr ? r1 : r0;
                    int b = row >> 12, nn = row & 4095;
                    long long dst = (((long long)((b << 3) + h)) * N_ + nn) * DH_ + d;
                    float2 v = rr ? make_float2(sc * acc[i][j][2], sc * acc[i][j][3])
                                  : make_float2(sc * acc[i][j][0], sc * acc[i][j][1]);
                    *(float2*)(dstbuf + dst) = v;
                }
            } else {
                int b = bz >> 3, h = bz & 7;
                *(float2*)(g_ctx + ((long long)(b * N_ + r0)) * DIM_ + h * DH_ + cc) =
                    make_float2(acc[i][j][0], acc[i][j][1]);
                *(float2*)(g_ctx + ((long long)(b * N_ + r1)) * DIM_ + h * DH_ + cc) =
                    make_float2(acc[i][j][2], acc[i][j][3]);
            }
        }
    }
}

// ---------------- sim GEMM (TB) with fused full-row softmax ------------------
// 256 threads, 2x4 warps, warp tile 32x64. BM=64, BN=256 (full landmark dim).
__global__ __launch_bounds__(256) void sim_softmax_kernel(
    const float* __restrict__ A, const float* __restrict__ Bm,
    float* __restrict__ C, int Kdim,
    long long sA, long long sB, long long sC)
{
    constexpr int BMs = 64, BNs = 256;
    __shared__ __align__(16) float As[BMs * RS];
    __shared__ __align__(16) float Bs[BNs * RS];
    __shared__ float redM[4][BMs];
    __shared__ float redS[4][BMs];

    int bz = blockIdx.z;
    const float* Ab = A + (long long)bz * sA;
    const float* Bb = Bm + (long long)bz * sB;
    float*       Cb = C + (long long)bz * sC;

    int m0 = blockIdx.y * BMs;
    int tid  = threadIdx.x;
    int wid  = tid >> 5;
    int lane = tid & 31;
    int wm = wid >> 2, wn = wid & 3;
    int tm0 = wm * 32, tn0 = wn * 64;
    int g  = lane >> 2;
    int tg = lane & 3;

    float acc[2][8][4];
    #pragma unroll
    for (int i = 0; i < 2; i++)
        #pragma unroll
        for (int j = 0; j < 8; j++)
            #pragma unroll
            for (int c = 0; c < 4; c++) acc[i][j][c] = 0.f;

    for (int k0 = 0; k0 < Kdim; k0 += BK2) {
        {   // A: 64x16 = 256 chunks, exactly 1 per thread
            int m = tid >> 2, kq = (tid & 3) * 4;
            cpa16(&As[m * RS + kq], Ab + (long long)(m0 + m) * Kdim + k0 + kq);
        }
        #pragma unroll
        for (int c = 0; c < 4; c++) {   // B: 256x16 = 1024 chunks
            int id = c * 256 + tid;
            int n = id >> 2, kq = (id & 3) * 4;
            cpa16(&Bs[n * RS + kq], Bb + (long long)n * Kdim + k0 + kq);
        }
        CP_COMMIT();
        CP_WAIT0();
        __syncthreads();

        #pragma unroll
        for (int kk = 0; kk < BK2; kk += 8) {
            int c0 = kk + tg, c1 = c0 + 4;
            uint32_t af[2][4], bf[8][2];
            #pragma unroll
            for (int i = 0; i < 2; i++) {
                int r0 = (tm0 + i * 16 + g) * RS;
                int r1 = r0 + 8 * RS;
                af[i][0] = __float_as_uint(As[r0 + c0]);
                af[i][1] = __float_as_uint(As[r1 + c0]);
                af[i][2] = __float_as_uint(As[r0 + c1]);
                af[i][3] = __float_as_uint(As[r1 + c1]);
            }
            #pragma unroll
            for (int j = 0; j < 8; j++) {
                int rn = (tn0 + j * 8 + g) * RS;
                bf[j][0] = __float_as_uint(Bs[rn + c0]);
                bf[j][1] = __float_as_uint(Bs[rn + c1]);
            }
            #pragma unroll
            for (int i = 0; i < 2; i++)
                #pragma unroll
                for (int j = 0; j < 8; j++)
                    mma_tf32(acc[i][j][0], acc[i][j][1], acc[i][j][2], acc[i][j][3],
                             af[i][0], af[i][1], af[i][2], af[i][3],
                             bf[j][0], bf[j][1]);
        }
        __syncthreads();
    }

    // fused softmax over the full 256-wide row
    #pragma unroll
    for (int i = 0; i < 2; i++) {
        float mx0 = -1e30f, mx1 = -1e30f;
        #pragma unroll
        for (int j = 0; j < 8; j++) {
            mx0 = fmaxf(mx0, fmaxf(acc[i][j][0], acc[i][j][1]));
            mx1 = fmaxf(mx1, fmaxf(acc[i][j][2], acc[i][j][3]));
        }
        mx0 = fmaxf(mx0, __shfl_xor_sync(0xffffffffu, mx0, 1));
        mx0 = fmaxf(mx0, __shfl_xor_sync(0xffffffffu, mx0, 2));
        mx1 = fmaxf(mx1, __shfl_xor_sync(0xffffffffu, mx1, 1));
        mx1 = fmaxf(mx1, __shfl_xor_sync(0xffffffffu, mx1, 2));
        if (tg == 0) {
            redM[wn][tm0 + i * 16 + g]     = mx0;
            redM[wn][tm0 + i * 16 + g + 8] = mx1;
        }
    }
    __syncthreads();
    #pragma unroll
    for (int i = 0; i < 2; i++) {
        int rb0 = tm0 + i * 16 + g, rb1 = rb0 + 8;
        float mx0 = fmaxf(fmaxf(redM[0][rb0], redM[1][rb0]),
                          fmaxf(redM[2][rb0], redM[3][rb0]));
        float mx1 = fmaxf(fmaxf(redM[0][rb1], redM[1][rb1]),
                          fmaxf(redM[2][rb1], redM[3][rb1]));
        float s0 = 0.f, s1 = 0.f;
        #pragma unroll
        for (int j = 0; j < 8; j++) {
            float e0 = __expf(acc[i][j][0] - mx0);
            float e1 = __expf(acc[i][j][1] - mx0);
            float e2 = __expf(acc[i][j][2] - mx1);
            float e3 = __expf(acc[i][j][3] - mx1);
            acc[i][j][0] = e0; acc[i][j][1] = e1;
            acc[i][j][2] = e2; acc[i][j][3] = e3;
            s0 += e0 + e1; s1 += e2 + e3;
        }
        s0 += __shfl_xor_sync(0xffffffffu, s0, 1);
        s0 += __shfl_xor_sync(0xffffffffu, s0, 2);
        s1 += __shfl_xor_sync(0xffffffffu, s1, 1);
        s1 += __shfl_xor_sync(0xffffffffu, s1, 2);
        if (tg == 0) { redS[wn][rb0] = s0; redS[wn][rb1] = s1; }
    }
    __syncthreads();
    #pragma unroll
    for (int i = 0; i < 2; i++) {
        int rb0 = tm0 + i * 16 + g, rb1 = rb0 + 8;
        float i0 = 1.f / (redS[0][rb0] + redS[1][rb0] + redS[2][rb0] + redS[3][rb0]);
        float i1 = 1.f / (redS[0][rb1] + redS[1][rb1] + redS[2][rb1] + redS[3][rb1]);
        int r0 = m0 + rb0, r1 = m0 + rb1;
        #pragma unroll
        for (int j = 0; j < 8; j++) {
            int cc = tn0 + j * 8 + tg * 2;
            *(float2*)(Cb + (long long)r0 * 256 + cc) =
                make_float2(acc[i][j][0] * i0, acc[i][j][1] * i0);
            *(float2*)(Cb + (long long)r1 * 256 + cc) =
                make_float2(acc[i][j][2] * i1, acc[i][j][3] * i1);
        }
    }
}

// ---------------- landmark means ---------------------------------------------
__global__ __launch_bounds__(256) void landmark_kernel()
{
    int id = blockIdx.x * 256 + threadIdx.x;
    const int half = BH_ * M_ * DH_;
    bool isK = id >= half;
    int t = isK ? id - half : id;
    int d  = t & 63;
    int m  = (t >> 6) & 255;
    int bh = t >> 14;
    const float* src = (isK ? g_k : g_q) + ((long long)bh * N_ + m * L_) * DH_ + d;
    float s = 0.f;
    #pragma unroll
    for (int l = 0; l < L_; l++) s += src[l * DH_];
    (isK ? g_kl : g_ql)[t] = s * (1.0f / L_);
}

// ---------------- exp-softmax pass for a3 (writes exp, saves row sums) -------
__global__ __launch_bounds__(256) void softmax_e_kernel(
    float* __restrict__ x, float* __restrict__ sums)
{
    __shared__ float sh[256];
    float* row = x + (long long)blockIdx.x * N_;
    int tid = threadIdx.x;
    float m = -1e30f;
    #pragma unroll
    for (int i = 0; i < 4; i++) {
        float4 v = *(float4*)(row + (i * 256 + tid) * 4);
        m = fmaxf(m, fmaxf(fmaxf(v.x, v.y), fmaxf(v.z, v.w)));
    }
    m = blockReduceMax(m, sh);
    float s = 0.f;
    #pragma unroll
    for (int i = 0; i < 4; i++) {
        float4 v = *(float4*)(row + (i * 256 + tid) * 4);
        v.x = __expf(v.x - m); v.y = __expf(v.y - m);
        v.z = __expf(v.z - m); v.w = __expf(v.w - m);
        *(float4*)(row + (i * 256 + tid) * 4) = v;
        s += v.x + v.y + v.z + v.w;
    }
    s = blockReduceSum(s, sh);
    if (tid == 0) sums[blockIdx.x] = s;
}

// ---------------- a3v split-K reduce + row normalize -------------------------
__global__ __launch_bounds__(256) void a3v_reduce_kernel()
{
    int idx = blockIdx.x * 256 + threadIdx.x;
    int rrow = idx >> 6;
    int bh = idx >> 14;
    int inner = idx & 16383;
    long long base = (long long)bh * 4 * 16384 + inner;
    float s = g_part[base] + g_part[base + 16384]
            + g_part[base + 2 * 16384] + g_part[base + 3 * 16384];
    g_a3v[idx] = s / g_rsum[rrow];
}

// ---------------- pinv init ---------------------------------------------------
__global__ void zero_max_kernel() { g_max[0] = 0.f; g_max[1] = 0.f; }

__global__ __launch_bounds__(256) void pinv_absmax_kernel()
{
    __shared__ float sh[256];
    const float* X = g_a2 + (long long)blockIdx.x * (M_ * M_);
    int tid = threadIdx.x;
    float cs = 0.f, rs = 0.f;
    for (int j = 0; j < M_; j++) cs += fabsf(X[tid * M_ + j]);
    for (int i = 0; i < M_; i++) rs += fabsf(X[i * M_ + tid]);
    float cm = blockReduceMax(cs, sh);
    float rm = blockReduceMax(rs, sh);
    if (tid == 0) {
        atomicMax(reinterpret_cast<int*>(&g_max[0]), __float_as_int(cm));
        atomicMax(reinterpret_cast<int*>(&g_max[1]), __float_as_int(rm));
    }
}

__global__ __launch_bounds__(256) void zinit_kernel()
{
    long long id = (long long)blockIdx.x * 256 + threadIdx.x;
    float inv = 1.0f / (g_max[0] * g_max[1]);
    long long bh = id >> 16;
    int rem = (int)(id & 65535);
    int row = rem >> 8, col = rem & 255;
    g_z0[id] = g_a2[bh * (M_ * M_) + (long long)col * M_ + row] * inv;
}

// ---------------- depthwise conv residual added into ctx ----------------------
__global__ __launch_bounds__(256) void conv_add_kernel(const float* __restrict__ cw)
{
    long long id = (long long)blockIdx.x * 256 + threadIdx.x;
    int d = (int)(id & 63);
    int i = (int)((id >> 6) & 4095);
    int bh = (int)(id >> 18);
    int h = bh & 7, b = bh >> 3;
    const float* vb = g_v + ((long long)bh << 18);
    float acc = 0.f;
    #pragma unroll
    for (int k = 0; k < 33; k++) {
        int s = i + k - 16;
        if ((unsigned)s < (unsigned)N_) acc += cw[h * 33 + k] * vb[(long long)s * DH_ + d];
    }
    g_ctx[((long long)(b * N_ + i)) * DIM_ + h * DH_ + d] += acc;
}

// ---------------- host helpers -------------------------------------------------
static float* symaddr(const void* sym) {
    void* p = nullptr;
    cudaGetSymbolAddress(&p, sym);
    return (float*)p;
}

template<int MODE>
static void gemm(const float* A, const float* B, float* C,
                 int M, int N, int K, int batch, int ldA, int ldB,
                 long long sA, long long sB, long long sC, bool tb,
                 float alpha = 1.f,
                 const float* resid = nullptr, float rs = 0.f,
                 const float* rsPtr = nullptr,
                 const float* bias = nullptr)
{
    dim3 block(128);
    if (N % 128 == 0) {
        dim3 grid(N / 128, M / 128, batch);
        if (tb)
            mma_gemm_kernel<128, 128, true , MODE, false><<<grid, block>>>(
                A, B, C, N, K, ldA, ldB, sA, sB, sC, alpha, resid, rs, rsPtr, bias);
        else
            mma_gemm_kernel<128, 128, false, MODE, false><<<grid, block>>>(
                A, B, C, N, K, ldA, ldB, sA, sB, sC, alpha, resid, rs, rsPtr, bias);
    } else {
        dim3 grid(N / 64, M / 128, batch);
        if (tb)
            mma_gemm_kernel<128, 64, true , MODE, false><<<grid, block>>>(
                A, B, C, N, K, ldA, ldB, sA, sB, sC, alpha, resid, rs, rsPtr, bias);
        else
            mma_gemm_kernel<128, 64, false, MODE, false><<<grid, block>>>(
                A, B, C, N, K, ldA, ldB, sA, sB, sC, alpha, resid, rs, rsPtr, bias);
    }
}

extern "C" void kernel_launch(void* const* d_in, const int* in_sizes, int n_in,
                              void* d_out, int out_size)
{
    const float* x      = (const float*)d_in[0];
    const float* ln_w   = (const float*)d_in[1];
    const float* ln_b   = (const float*)d_in[2];
    const float* w_qkv  = (const float*)d_in[3];
    const float* w_out  = (const float*)d_in[4];
    const float* b_out  = (const float*)d_in[5];
    const float* conv_w = (const float*)d_in[6];
    const float* omega  = (const float*)d_in[7];
    float* out = (float*)d_out;

    float* p_ln   = symaddr(g_ln);
    float* p_q    = symaddr(g_q);
    float* p_k    = symaddr(g_k);
    float* p_v    = symaddr(g_v);
    float* p_ql   = symaddr(g_ql);
    float* p_kl   = symaddr(g_kl);
    float* p_a1   = symaddr(g_a1);
    float* p_a3   = symaddr(g_a3);
    float* p_a2   = symaddr(g_a2);
    float* p_z0   = symaddr(g_z0);
    float* p_z1   = symaddr(g_z1);
    float* p_t1   = symaddr(g_t1);
    float* p_t2   = symaddr(g_t2);
    float* p_t3   = symaddr(g_t3);
    float* p_a3v  = symaddr(g_a3v);
    float* p_part = symaddr(g_part);
    float* p_rsum = symaddr(g_rsum);
    float* p_ctx  = symaddr(g_ctx);

    const long long sQ  = (long long)N_ * DH_;
    const long long sL  = (long long)M_ * DH_;
    const long long sS1 = (long long)N_ * M_;
    const long long sA2 = (long long)M_ * M_;

    // 1) layernorm
    ln_kernel<<<ROWS_, 256>>>(x, ln_w, ln_b);

    // 2) qkv projection, epilogue writes q (scaled), k, v head-major
    gemm<1>(p_ln, w_qkv, nullptr, ROWS_, 3 * DIM_, DIM_, 1, DIM_, 3 * DIM_,
            0, 0, 0, false);

    // 3) landmarks
    landmark_kernel<<<(2 * BH_ * M_ * DH_) / 256, 256>>>();

    // 4) sim1 + softmax -> a1; sim2 + softmax -> a2
    {
        dim3 block(256);
        sim_softmax_kernel<<<dim3(1, N_ / 64, BH_), block>>>(
            p_q, p_kl, p_a1, DH_, sQ, sL, sS1);
        sim_softmax_kernel<<<dim3(1, M_ / 64, BH_), block>>>(
            p_ql, p_kl, p_a2, DH_, sL, sL, sA2);
    }

    // 5) sim3 -> a3, then exp pass with row sums
    gemm<0>(p_ql, p_k, p_a3, M_, N_, DH_, BH_, DH_, DH_, sL, sQ, sS1, true);
    softmax_e_kernel<<<BH_ * M_, 256>>>(p_a3, p_rsum);

    // 6) Moore-Penrose pinv of a2 (Newton-Schulz, 6 iters)
    zero_max_kernel<<<1, 1>>>();
    pinv_absmax_kernel<<<BH_, 256>>>();
    zinit_kernel<<<(BH_ * M_ * M_) / 256, 256>>>();

    for (int it = 0; it < 6; it++) {
        float* zin  = (it & 1) ? p_z1 : p_z0;
        float* zout = (it & 1) ? p_z0 : p_z1;
        gemm<0>(p_a2, zin, p_t1, M_, M_, M_, BH_, M_, M_, sA2, sA2, sA2, false);
        gemm<0>(p_t1, p_t1, p_t2, M_, M_, M_, BH_, M_, M_, sA2, sA2, sA2, false,
                -1.f, p_t1, 7.f);
        gemm<0>(p_t1, p_t2, p_t3, M_, M_, M_, BH_, M_, M_, sA2, sA2, sA2, false,
                -1.f, p_t1, 15.f);
        gemm<0>(zin, p_t3, zout, M_, M_, M_, BH_, M_, M_, sA2, sA2, sA2, false,
                -0.25f, zin, 3.25f);
    }

    // 7) a3v = (exp(sim3) @ v) / rowsum, split-K x4
    {
        dim3 grid(1, M_ / 128, BH_ * 4), block(128);
        mma_gemm_kernel<128, 64, false, 0, true><<<grid, block>>>(
            p_a3, p_v, p_part, DH_, N_ / 4, N_, DH_, sS1, sQ, sL,
            1.f, nullptr, 0.f, nullptr, nullptr);
        a3v_reduce_kernel<<<(BH_ * M_ * DH_) / 256, 256>>>();
    }

    // 8) a1 @ a2inv -> reuse g_a3 ([n, m])
    gemm<0>(p_a1, p_z0, p_a3, N_, M_, M_, BH_, M_, M_, sS1, sA2, sS1, false);

    // 9) (a1 a2inv) @ a3v -> ctx layout directly
    gemm<2>(p_a3, p_a3v, nullptr, N_, DH_, M_, BH_, M_, DH_, sS1, sL, 0, false);

    // 10) depthwise conv residual added into ctx
    conv_add_kernel<<<(BH_ * N_ * DH_) / 256, 256>>>(conv_w);

    // 11) output projection + bias + omega * x
    gemm<0>(p_ctx, w_out, out, ROWS_, DIM_, DIM_, 1, DIM_, DIM_, 0, 0, 0, false,
            1.f, x, 0.f, omega, b_out);
}

// round 7
// speedup vs baseline: 2.5793x; 1.1503x over previous
#include <cuda_runtime.h>
#include <cuda_bf16.h>
#include <cstdint>

// ---------------------------------------------------------------------------
// Nystrom attention transformer layer. TF32 mma GEMMs, 64x64 warp tiles,
// cp.async, conflict-free smem. Reassociated output chain, exp fused in GEMM.
// ---------------------------------------------------------------------------

#define B_    4
#define N_    4096
#define DIM_  512
#define H_    8
#define DH_   64
#define M_    256
#define L_    16
#define ROWS_ (B_ * N_)          // 16384
#define BH_   (B_ * H_)          // 32

// ---------------- scratch (device globals) ----------------------------------
__device__ float g_ln  [ROWS_ * DIM_];
__device__ float g_q   [BH_ * N_ * DH_];
__device__ float g_k   [BH_ * N_ * DH_];
__device__ float g_v   [BH_ * N_ * DH_];
__device__ float g_ql  [BH_ * M_ * DH_];
__device__ float g_kl  [BH_ * M_ * DH_];
__device__ float g_a1  [BH_ * N_ * M_];
__device__ float g_a3  [BH_ * M_ * N_];     // exp(sim3)
__device__ float g_a2  [BH_ * M_ * M_];
__device__ float g_z0  [BH_ * M_ * M_];
__device__ float g_z1  [BH_ * M_ * M_];
__device__ float g_t1  [BH_ * M_ * M_];
__device__ float g_t2  [BH_ * M_ * M_];
__device__ float g_t3  [BH_ * M_ * M_];
__device__ float g_a3v [BH_ * M_ * DH_];
__device__ float g_w   [BH_ * M_ * DH_];    // a2inv @ a3v
__device__ float g_part[BH_ * 4 * M_ * DH_];
__device__ float g_rsum[BH_ * M_];
__device__ float g_ctx [ROWS_ * DIM_];
__device__ float g_max [2];

// ---------------- reductions -------------------------------------------------
__device__ __forceinline__ float blockReduceSum(float v, float* sh) {
    int tid = threadIdx.x;
    sh[tid] = v; __syncthreads();
    for (int s = 128; s > 0; s >>= 1) {
        if (tid < s) sh[tid] += sh[tid + s];
        __syncthreads();
    }
    float r = sh[0]; __syncthreads();
    return r;
}
__device__ __forceinline__ float blockReduceMax(float v, float* sh) {
    int tid = threadIdx.x;
    sh[tid] = v; __syncthreads();
    for (int s = 128; s > 0; s >>= 1) {
        if (tid < s) sh[tid] = fmaxf(sh[tid], sh[tid + s]);
        __syncthreads();
    }
    float r = sh[0]; __syncthreads();
    return r;
}

// ---------------- layernorm --------------------------------------------------
__global__ __launch_bounds__(256) void ln_kernel(
    const float* __restrict__ x, const float* __restrict__ w,
    const float* __restrict__ b)
{
    __shared__ float sh[256];
    long long r = blockIdx.x;
    const float* xr = x + r * DIM_;
    int tid = threadIdx.x;
    float v0 = xr[tid], v1 = xr[tid + 256];
    float s = blockReduceSum(v0 + v1, sh);
    float mu = s * (1.0f / DIM_);
    float d0 = v0 - mu, d1 = v1 - mu;
    float s2 = blockReduceSum(d0 * d0 + d1 * d1, sh);
    float inv = rsqrtf(s2 * (1.0f / DIM_) + 1e-5f);
    g_ln[r * DIM_ + tid]        = d0 * inv * w[tid] + b[tid];
    g_ln[r * DIM_ + tid + 256]  = d1 * inv * w[tid + 256] + b[tid + 256];
}

// ---------------- mma + cp.async helpers -------------------------------------
__device__ __forceinline__ void mma_tf32(
    float& c0, float& c1, float& c2, float& c3,
    uint32_t a0, uint32_t a1, uint32_t a2, uint32_t a3,
    uint32_t b0, uint32_t b1)
{
    asm volatile(
        "mma.sync.aligned.m16n8k8.row.col.f32.tf32.tf32.f32 "
        "{%0,%1,%2,%3}, {%4,%5,%6,%7}, {%8,%9}, {%0,%1,%2,%3};"
        : "+f"(c0), "+f"(c1), "+f"(c2), "+f"(c3)
        : "r"(a0), "r"(a1), "r"(a2), "r"(a3), "r"(b0), "r"(b1));
}
__device__ __forceinline__ void cpa16(void* dst, const void* src) {
    uint32_t d = (uint32_t)__cvta_generic_to_shared(dst);
    asm volatile("cp.async.cg.shared.global [%0], [%1], 16;" :: "r"(d), "l"(src));
}
#define CP_COMMIT() asm volatile("cp.async.commit_group;" ::: "memory")
#define CP_WAIT1()  asm volatile("cp.async.wait_group 1;" ::: "memory")
#define CP_WAIT0()  asm volatile("cp.async.wait_group 0;" ::: "memory")

#define BK2 16
#define RS  20      // [row][k] stride (words): frag banks 20g+tg = all 32 distinct

// ---------------- main mma GEMM: 128 threads, 2x2 warps, 64x64 warp tile -----
// MODE 0: standard epilogue; MODE 1: qkv split; MODE 2: ctx layout;
// MODE 3: exp + atomic row sums (for sim3).
// SPLITK: blockIdx.z = bh*4 + split, Kdim = chunk length.
template<int BM, int BN, bool TB, int MODE, bool SPLITK>
__global__ __launch_bounds__(128, 2) void mma_gemm_kernel(
    const float* __restrict__ A, const float* __restrict__ B,
    float* __restrict__ C, int Ndim, int Kdim, int ldA, int ldB,
    long long sA, long long sB, long long sC,
    float alpha,
    const float* __restrict__ resid, float residScale,
    const float* __restrict__ residScalePtr,
    const float* __restrict__ bias)
{
    constexpr int MT = 4;               // 64 rows / 16
    constexpr int NT = BN / 16;         // (BN/2) / 8
    constexpr int RSB = BN + 8;         // [k][n] stride: frag banks 8tg+g distinct
    constexpr int ASZ = BM * RS;
    constexpr int BSZ = TB ? BN * RS : BK2 * RSB;

    __shared__ __align__(16) float As[2][ASZ];
    __shared__ __align__(16) float Bs[2][BSZ];

    int bz = blockIdx.z;
    long long aOff, bOff, cOff;
    if (SPLITK) {
        int bz0 = bz >> 2, sp = bz & 3;
        aOff = (long long)bz0 * sA + (long long)sp * Kdim;
        bOff = (long long)bz0 * sB + (long long)sp * Kdim * ldB;
        cOff = (long long)bz * sC;
    } else {
        aOff = (long long)bz * sA;
        bOff = (long long)bz * sB;
        cOff = (long long)bz * sC;
    }
    const float* Ab = A + aOff;
    const float* Bb = B + bOff;
    float*       Cb = C + cOff;
    const float* Rb = resid ? resid + cOff : nullptr;

    int n0 = blockIdx.x * BN;
    int m0 = blockIdx.y * BM;
    int tid  = threadIdx.x;
    int wid  = tid >> 5;
    int lane = tid & 31;
    int wm = wid >> 1, wn = wid & 1;
    int tm0 = wm * 64, tn0 = wn * (BN / 2);
    int g  = lane >> 2;
    int tg = lane & 3;

    float acc[MT][NT][4];
    #pragma unroll
    for (int i = 0; i < MT; i++)
        #pragma unroll
        for (int j = 0; j < NT; j++)
            #pragma unroll
            for (int c = 0; c < 4; c++) acc[i][j][c] = 0.f;

    auto loadTile = [&](int t, int st) {
        int k0 = t * BK2;
        #pragma unroll
        for (int c = 0; c < BM / 32; c++) {
            int id = c * 128 + tid;
            int m = id >> 2, kq = (id & 3) * 4;
            cpa16(&As[st][m * RS + kq],
                  Ab + (long long)(m0 + m) * ldA + k0 + kq);
        }
        if (TB) {
            #pragma unroll
            for (int c = 0; c < BN / 32; c++) {
                int id = c * 128 + tid;
                int n = id >> 2, kq = (id & 3) * 4;
                cpa16(&Bs[st][n * RS + kq],
                      Bb + (long long)(n0 + n) * ldB + k0 + kq);
            }
        } else {
            constexpr int CPR = BN / 4;   // 16B chunks per k-row
            #pragma unroll
            for (int c = 0; c < BN / 32; c++) {
                int id = c * 128 + tid;
                int k = id / CPR, nq = (id % CPR) * 4;
                cpa16(&Bs[st][k * RSB + nq],
                      Bb + (long long)(k0 + k) * ldB + n0 + nq);
            }
        }
    };

    auto computeStage = [&](int st) {
        const float* as = As[st];
        const float* bs = Bs[st];
        #pragma unroll
        for (int kk = 0; kk < BK2; kk += 8) {
            int c0 = kk + tg, c1 = c0 + 4;
            uint32_t af[MT][4], bf[NT][2];
            #pragma unroll
            for (int i = 0; i < MT; i++) {
                int r0 = (tm0 + i * 16 + g) * RS;
                int r1 = r0 + 8 * RS;
                af[i][0] = __float_as_uint(as[r0 + c0]);
                af[i][1] = __float_as_uint(as[r1 + c0]);
                af[i][2] = __float_as_uint(as[r0 + c1]);
                af[i][3] = __float_as_uint(as[r1 + c1]);
            }
            #pragma unroll
            for (int j = 0; j < NT; j++) {
                if (TB) {
                    int rn = (tn0 + j * 8 + g) * RS;
                    bf[j][0] = __float_as_uint(bs[rn + c0]);
                    bf[j][1] = __float_as_uint(bs[rn + c1]);
                } else {
                    int b0 = c0 * RSB + tn0 + j * 8 + g;
                    bf[j][0] = __float_as_uint(bs[b0]);
                    bf[j][1] = __float_as_uint(bs[b0 + 4 * RSB]);
                }
            }
            #pragma unroll
            for (int i = 0; i < MT; i++)
                #pragma unroll
                for (int j = 0; j < NT; j++)
                    mma_tf32(acc[i][j][0], acc[i][j][1], acc[i][j][2], acc[i][j][3],
                             af[i][0], af[i][1], af[i][2], af[i][3],
                             bf[j][0], bf[j][1]);
        }
    };

    int nIter = Kdim / BK2;
    loadTile(0, 0); CP_COMMIT();
    loadTile(1, 1); CP_COMMIT();
    int p = 0;
    for (int t = 0; t < nIter; t++) {
        CP_WAIT1();
        __syncthreads();
        computeStage(p);
        __syncthreads();
        if (t + 2 < nIter) loadTile(t + 2, p);
        CP_COMMIT();
        p ^= 1;
    }

    // ---------------- epilogue ----------------
    if (MODE == 3) {
        // exp(values) + per-row partial sums -> atomicAdd into g_rsum
        #pragma unroll
        for (int i = 0; i < MT; i++) {
            int r0 = m0 + tm0 + i * 16 + g;
            int r1 = r0 + 8;
            float s0 = 0.f, s1 = 0.f;
            #pragma unroll
            for (int j = 0; j < NT; j++) {
                int cc = n0 + tn0 + j * 8 + tg * 2;
                float e0 = __expf(acc[i][j][0]);
                float e1 = __expf(acc[i][j][1]);
                float e2 = __expf(acc[i][j][2]);
                float e3 = __expf(acc[i][j][3]);
                *(float2*)(Cb + (long long)r0 * Ndim + cc) = make_float2(e0, e1);
                *(float2*)(Cb + (long long)r1 * Ndim + cc) = make_float2(e2, e3);
                s0 += e0 + e1; s1 += e2 + e3;
            }
            s0 += __shfl_xor_sync(0xffffffffu, s0, 1);
            s0 += __shfl_xor_sync(0xffffffffu, s0, 2);
            s1 += __shfl_xor_sync(0xffffffffu, s1, 1);
            s1 += __shfl_xor_sync(0xffffffffu, s1, 2);
            if (tg == 0) {
                atomicAdd(&g_rsum[bz * M_ + r0], s0);
                atomicAdd(&g_rsum[bz * M_ + r1], s1);
            }
        }
        return;
    }

    float rs = residScalePtr ? *residScalePtr : residScale;
    #pragma unroll
    for (int i = 0; i < MT; i++) {
        int r0 = m0 + tm0 + i * 16 + g;
        int r1 = r0 + 8;
        #pragma unroll
        for (int j = 0; j < NT; j++) {
            int cc = n0 + tn0 + j * 8 + tg * 2;
            if (MODE == 0) {
                float2 bv = bias ? *(const float2*)(bias + cc) : make_float2(0.f, 0.f);
                float2 v0 = make_float2(alpha * acc[i][j][0] + bv.x,
                                        alpha * acc[i][j][1] + bv.y);
                float2 v1 = make_float2(alpha * acc[i][j][2] + bv.x,
                                        alpha * acc[i][j][3] + bv.y);
                if (Rb) {
                    float2 q0 = *(const float2*)(Rb + (long long)r0 * Ndim + cc);
                    float2 q1 = *(const float2*)(Rb + (long long)r1 * Ndim + cc);
                    v0.x += rs * q0.x; v0.y += rs * q0.y;
                    v1.x += rs * q1.x; v1.y += rs * q1.y;
                }
                *(float2*)(Cb + (long long)r0 * Ndim + cc) = v0;
                *(float2*)(Cb + (long long)r1 * Ndim + cc) = v1;
            } else if (MODE == 1) {
                int which = cc >> 9;
                int hc = cc & 511;
                int h = hc >> 6, d = hc & 63;
                float sc = (which == 0) ? 0.125f : 1.0f;
                float* dstbuf = (which == 0) ? g_q : (which == 1) ? g_k : g_v;
                #pragma unroll
                for (int rr = 0; rr < 2; rr++) {
                    int row = rr ? r1 : r0;
                    int b = row >> 12, nn = row & 4095;
                    long long dst = (((long long)((b << 3) + h)) * N_ + nn) * DH_ + d;
                    float2 v = rr ? make_float2(sc * acc[i][j][2], sc * acc[i][j][3])
                                  : make_float2(sc * acc[i][j][0], sc * acc[i][j][1]);
                    *(float2*)(dstbuf + dst) = v;
                }
            } else {
                int b = bz >> 3, h = bz & 7;
                *(float2*)(g_ctx + ((long long)(b * N_ + r0)) * DIM_ + h * DH_ + cc) =
                    make_float2(acc[i][j][0], acc[i][j][1]);
                *(float2*)(g_ctx + ((long long)(b * N_ + r1)) * DIM_ + h * DH_ + cc) =
                    make_float2(acc[i][j][2], acc[i][j][3]);
            }
        }
    }
}

// ---------------- sim GEMM (TB) with fused full-row softmax ------------------
// 256 threads, 2x4 warps, warp tile 32x64. BM=64, BN=256 (full landmark dim).
__global__ __launch_bounds__(256) void sim_softmax_kernel(
    const float* __restrict__ A, const float* __restrict__ Bm,
    float* __restrict__ C, int Kdim,
    long long sA, long long sB, long long sC)
{
    constexpr int BMs = 64, BNs = 256;
    __shared__ __align__(16) float As[BMs * RS];
    __shared__ __align__(16) float Bs[BNs * RS];
    __shared__ float redM[4][BMs];
    __shared__ float redS[4][BMs];

    int bz = blockIdx.z;
    const float* Ab = A + (long long)bz * sA;
    const float* Bb = Bm + (long long)bz * sB;
    float*       Cb = C + (long long)bz * sC;

    int m0 = blockIdx.y * BMs;
    int tid  = threadIdx.x;
    int wid  = tid >> 5;
    int lane = tid & 31;
    int wm = wid >> 2, wn = wid & 3;
    int tm0 = wm * 32, tn0 = wn * 64;
    int g  = lane >> 2;
    int tg = lane & 3;

    float acc[2][8][4];
    #pragma unroll
    for (int i = 0; i < 2; i++)
        #pragma unroll
        for (int j = 0; j < 8; j++)
            #pragma unroll
            for (int c = 0; c < 4; c++) acc[i][j][c] = 0.f;

    for (int k0 = 0; k0 < Kdim; k0 += BK2) {
        {
            int m = tid >> 2, kq = (tid & 3) * 4;
            cpa16(&As[m * RS + kq], Ab + (long long)(m0 + m) * Kdim + k0 + kq);
        }
        #pragma unroll
        for (int c = 0; c < 4; c++) {
            int id = c * 256 + tid;
            int n = id >> 2, kq = (id & 3) * 4;
            cpa16(&Bs[n * RS + kq], Bb + (long long)n * Kdim + k0 + kq);
        }
        CP_COMMIT();
        CP_WAIT0();
        __syncthreads();

        #pragma unroll
        for (int kk = 0; kk < BK2; kk += 8) {
            int c0 = kk + tg, c1 = c0 + 4;
            uint32_t af[2][4], bf[8][2];
            #pragma unroll
            for (int i = 0; i < 2; i++) {
                int r0 = (tm0 + i * 16 + g) * RS;
                int r1 = r0 + 8 * RS;
                af[i][0] = __float_as_uint(As[r0 + c0]);
                af[i][1] = __float_as_uint(As[r1 + c0]);
                af[i][2] = __float_as_uint(As[r0 + c1]);
                af[i][3] = __float_as_uint(As[r1 + c1]);
            }
            #pragma unroll
            for (int j = 0; j < 8; j++) {
                int rn = (tn0 + j * 8 + g) * RS;
                bf[j][0] = __float_as_uint(Bs[rn + c0]);
                bf[j][1] = __float_as_uint(Bs[rn + c1]);
            }
            #pragma unroll
            for (int i = 0; i < 2; i++)
                #pragma unroll
                for (int j = 0; j < 8; j++)
                    mma_tf32(acc[i][j][0], acc[i][j][1], acc[i][j][2], acc[i][j][3],
                             af[i][0], af[i][1], af[i][2], af[i][3],
                             bf[j][0], bf[j][1]);
        }
        __syncthreads();
    }

    #pragma unroll
    for (int i = 0; i < 2; i++) {
        float mx0 = -1e30f, mx1 = -1e30f;
        #pragma unroll
        for (int j = 0; j < 8; j++) {
            mx0 = fmaxf(mx0, fmaxf(acc[i][j][0], acc[i][j][1]));
            mx1 = fmaxf(mx1, fmaxf(acc[i][j][2], acc[i][j][3]));
        }
        mx0 = fmaxf(mx0, __shfl_xor_sync(0xffffffffu, mx0, 1));
        mx0 = fmaxf(mx0, __shfl_xor_sync(0xffffffffu, mx0, 2));
        mx1 = fmaxf(mx1, __shfl_xor_sync(0xffffffffu, mx1, 1));
        mx1 = fmaxf(mx1, __shfl_xor_sync(0xffffffffu, mx1, 2));
        if (tg == 0) {
            redM[wn][tm0 + i * 16 + g]     = mx0;
            redM[wn][tm0 + i * 16 + g + 8] = mx1;
        }
    }
    __syncthreads();
    #pragma unroll
    for (int i = 0; i < 2; i++) {
        int rb0 = tm0 + i * 16 + g, rb1 = rb0 + 8;
        float mx0 = fmaxf(fmaxf(redM[0][rb0], redM[1][rb0]),
                          fmaxf(redM[2][rb0], redM[3][rb0]));
        float mx1 = fmaxf(fmaxf(redM[0][rb1], redM[1][rb1]),
                          fmaxf(redM[2][rb1], redM[3][rb1]));
        float s0 = 0.f, s1 = 0.f;
        #pragma unroll
        for (int j = 0; j < 8; j++) {
            float e0 = __expf(acc[i][j][0] - mx0);
            float e1 = __expf(acc[i][j][1] - mx0);
            float e2 = __expf(acc[i][j][2] - mx1);
            float e3 = __expf(acc[i][j][3] - mx1);
            acc[i][j][0] = e0; acc[i][j][1] = e1;
            acc[i][j][2] = e2; acc[i][j][3] = e3;
            s0 += e0 + e1; s1 += e2 + e3;
        }
        s0 += __shfl_xor_sync(0xffffffffu, s0, 1);
        s0 += __shfl_xor_sync(0xffffffffu, s0, 2);
        s1 += __shfl_xor_sync(0xffffffffu, s1, 1);
        s1 += __shfl_xor_sync(0xffffffffu, s1, 2);
        if (tg == 0) { redS[wn][rb0] = s0; redS[wn][rb1] = s1; }
    }
    __syncthreads();
    #pragma unroll
    for (int i = 0; i < 2; i++) {
        int rb0 = tm0 + i * 16 + g, rb1 = rb0 + 8;
        float i0 = 1.f / (redS[0][rb0] + redS[1][rb0] + redS[2][rb0] + redS[3][rb0]);
        float i1 = 1.f / (redS[0][rb1] + redS[1][rb1] + redS[2][rb1] + redS[3][rb1]);
        int r0 = m0 + rb0, r1 = m0 + rb1;
        #pragma unroll
        for (int j = 0; j < 8; j++) {
            int cc = tn0 + j * 8 + tg * 2;
            *(float2*)(Cb + (long long)r0 * 256 + cc) =
                make_float2(acc[i][j][0] * i0, acc[i][j][1] * i0);
            *(float2*)(Cb + (long long)r1 * 256 + cc) =
                make_float2(acc[i][j][2] * i1, acc[i][j][3] * i1);
        }
    }
}

// ---------------- landmark means ---------------------------------------------
__global__ __launch_bounds__(256) void landmark_kernel()
{
    int id = blockIdx.x * 256 + threadIdx.x;
    const int half = BH_ * M_ * DH_;
    bool isK = id >= half;
    int t = isK ? id - half : id;
    int d  = t & 63;
    int m  = (t >> 6) & 255;
    int bh = t >> 14;
    const float* src = (isK ? g_k : g_q) + ((long long)bh * N_ + m * L_) * DH_ + d;
    float s = 0.f;
    #pragma unroll
    for (int l = 0; l < L_; l++) s += src[l * DH_];
    (isK ? g_kl : g_ql)[t] = s * (1.0f / L_);
}

// ---------------- zero rsum ---------------------------------------------------
__global__ __launch_bounds__(256) void zero_rsum_kernel()
{
    g_rsum[blockIdx.x * 256 + threadIdx.x] = 0.f;
}

// ---------------- a3v split-K reduce + row normalize -------------------------
__global__ __launch_bounds__(256) void a3v_reduce_kernel()
{
    int idx = blockIdx.x * 256 + threadIdx.x;
    int rrow = idx >> 6;
    int bh = idx >> 14;
    int inner = idx & 16383;
    long long base = (long long)bh * 4 * 16384 + inner;
    float s = g_part[base] + g_part[base + 16384]
            + g_part[base + 2 * 16384] + g_part[base + 3 * 16384];
    g_a3v[idx] = s / g_rsum[rrow];
}

// ---------------- pinv init ---------------------------------------------------
__global__ void zero_max_kernel() { g_max[0] = 0.f; g_max[1] = 0.f; }

__global__ __launch_bounds__(256) void pinv_absmax_kernel()
{
    __shared__ float sh[256];
    const float* X = g_a2 + (long long)blockIdx.x * (M_ * M_);
    int tid = threadIdx.x;
    float cs = 0.f, rs = 0.f;
    for (int j = 0; j < M_; j++) cs += fabsf(X[tid * M_ + j]);
    for (int i = 0; i < M_; i++) rs += fabsf(X[i * M_ + tid]);
    float cm = blockReduceMax(cs, sh);
    float rm = blockReduceMax(rs, sh);
    if (tid == 0) {
        atomicMax(reinterpret_cast<int*>(&g_max[0]), __float_as_int(cm));
        atomicMax(reinterpret_cast<int*>(&g_max[1]), __float_as_int(rm));
    }
}

__global__ __launch_bounds__(256) void zinit_kernel()
{
    long long id = (long long)blockIdx.x * 256 + threadIdx.x;
    float inv = 1.0f / (g_max[0] * g_max[1]);
    long long bh = id >> 16;
    int rem = (int)(id & 65535);
    int row = rem >> 8, col = rem & 255;
    g_z0[id] = g_a2[bh * (M_ * M_) + (long long)col * M_ + row] * inv;
}

// ---------------- depthwise conv residual added into ctx ----------------------
__global__ __launch_bounds__(256) void conv_add_kernel(const float* __restrict__ cw)
{
    long long id = (long long)blockIdx.x * 256 + threadIdx.x;
    int d = (int)(id & 63);
    int i = (int)((id >> 6) & 4095);
    int bh = (int)(id >> 18);
    int h = bh & 7, b = bh >> 3;
    const float* vb = g_v + ((long long)bh << 18);
    float acc = 0.f;
    #pragma unroll
    for (int k = 0; k < 33; k++) {
        int s = i + k - 16;
        if ((unsigned)s < (unsigned)N_) acc += cw[h * 33 + k] * vb[(long long)s * DH_ + d];
    }
    g_ctx[((long long)(b * N_ + i)) * DIM_ + h * DH_ + d] += acc;
}

// ---------------- host helpers -------------------------------------------------
static float* symaddr(const void* sym) {
    void* p = nullptr;
    cudaGetSymbolAddress(&p, sym);
    return (float*)p;
}

template<int MODE>
static void gemm(const float* A, const float* B, float* C,
                 int M, int N, int K, int batch, int ldA, int ldB,
                 long long sA, long long sB, long long sC, bool tb,
                 float alpha = 1.f,
                 const float* resid = nullptr, float rs = 0.f,
                 const float* rsPtr = nullptr,
                 const float* bias = nullptr,
                 bool forceBN64 = false)
{
    dim3 block(128);
    if (N % 128 == 0 && !forceBN64) {
        dim3 grid(N / 128, M / 128, batch);
        if (tb)
            mma_gemm_kernel<128, 128, true , MODE, false><<<grid, block>>>(
                A, B, C, N, K, ldA, ldB, sA, sB, sC, alpha, resid, rs, rsPtr, bias);
        else
            mma_gemm_kernel<128, 128, false, MODE, false><<<grid, block>>>(
                A, B, C, N, K, ldA, ldB, sA, sB, sC, alpha, resid, rs, rsPtr, bias);
    } else {
        dim3 grid(N / 64, M / 128, batch);
        if (tb)
            mma_gemm_kernel<128, 64, true , MODE, false><<<grid, block>>>(
                A, B, C, N, K, ldA, ldB, sA, sB, sC, alpha, resid, rs, rsPtr, bias);
        else
            mma_gemm_kernel<128, 64, false, MODE, false><<<grid, block>>>(
                A, B, C, N, K, ldA, ldB, sA, sB, sC, alpha, resid, rs, rsPtr, bias);
    }
}

extern "C" void kernel_launch(void* const* d_in, const int* in_sizes, int n_in,
                              void* d_out, int out_size)
{
    const float* x      = (const float*)d_in[0];
    const float* ln_w   = (const float*)d_in[1];
    const float* ln_b   = (const float*)d_in[2];
    const float* w_qkv  = (const float*)d_in[3];
    const float* w_out  = (const float*)d_in[4];
    const float* b_out  = (const float*)d_in[5];
    const float* conv_w = (const float*)d_in[6];
    const float* omega  = (const float*)d_in[7];
    float* out = (float*)d_out;

    float* p_ln   = symaddr(g_ln);
    float* p_q    = symaddr(g_q);
    float* p_k    = symaddr(g_k);
    float* p_v    = symaddr(g_v);
    float* p_ql   = symaddr(g_ql);
    float* p_kl   = symaddr(g_kl);
    float* p_a1   = symaddr(g_a1);
    float* p_a3   = symaddr(g_a3);
    float* p_a2   = symaddr(g_a2);
    float* p_z0   = symaddr(g_z0);
    float* p_z1   = symaddr(g_z1);
    float* p_t1   = symaddr(g_t1);
    float* p_t2   = symaddr(g_t2);
    float* p_t3   = symaddr(g_t3);
    float* p_a3v  = symaddr(g_a3v);
    float* p_w    = symaddr(g_w);
    float* p_part = symaddr(g_part);
    float* p_ctx  = symaddr(g_ctx);

    const long long sQ  = (long long)N_ * DH_;
    const long long sL  = (long long)M_ * DH_;
    const long long sS1 = (long long)N_ * M_;
    const long long sA2 = (long long)M_ * M_;

    // 1) layernorm
    ln_kernel<<<ROWS_, 256>>>(x, ln_w, ln_b);

    // 2) qkv projection, epilogue writes q (scaled), k, v head-major
    gemm<1>(p_ln, w_qkv, nullptr, ROWS_, 3 * DIM_, DIM_, 1, DIM_, 3 * DIM_,
            0, 0, 0, false);

    // 3) landmarks
    landmark_kernel<<<(2 * BH_ * M_ * DH_) / 256, 256>>>();

    // 4) sim1 + softmax -> a1; sim2 + softmax -> a2
    {
        dim3 block(256);
        sim_softmax_kernel<<<dim3(1, N_ / 64, BH_), block>>>(
            p_q, p_kl, p_a1, DH_, sQ, sL, sS1);
        sim_softmax_kernel<<<dim3(1, M_ / 64, BH_), block>>>(
            p_ql, p_kl, p_a2, DH_, sL, sL, sA2);
    }

    // 5) sim3 -> exp(sim3) with fused row sums (no max-subtract; values bounded)
    zero_rsum_kernel<<<(BH_ * M_) / 256, 256>>>();
    gemm<3>(p_ql, p_k, p_a3, M_, N_, DH_, BH_, DH_, DH_, sL, sQ, sS1, true);

    // 6) Moore-Penrose pinv of a2 (Newton-Schulz, 6 iters), BN=64 for occupancy
    zero_max_kernel<<<1, 1>>>();
    pinv_absmax_kernel<<<BH_, 256>>>();
    zinit_kernel<<<(BH_ * M_ * M_) / 256, 256>>>();

    for (int it = 0; it < 6; it++) {
        float* zin  = (it & 1) ? p_z1 : p_z0;
        float* zout = (it & 1) ? p_z0 : p_z1;
        gemm<0>(p_a2, zin, p_t1, M_, M_, M_, BH_, M_, M_, sA2, sA2, sA2, false,
                1.f, nullptr, 0.f, nullptr, nullptr, true);
        gemm<0>(p_t1, p_t1, p_t2, M_, M_, M_, BH_, M_, M_, sA2, sA2, sA2, false,
                -1.f, p_t1, 7.f, nullptr, nullptr, true);
        gemm<0>(p_t1, p_t2, p_t3, M_, M_, M_, BH_, M_, M_, sA2, sA2, sA2, false,
                -1.f, p_t1, 15.f, nullptr, nullptr, true);
        gemm<0>(zin, p_t3, zout, M_, M_, M_, BH_, M_, M_, sA2, sA2, sA2, false,
                -0.25f, zin, 3.25f, nullptr, nullptr, true);
    }

    // 7) a3v = (exp(sim3) @ v) / rowsum, split-K x4
    {
        dim3 grid(1, M_ / 128, BH_ * 4), block(128);
        mma_gemm_kernel<128, 64, false, 0, true><<<grid, block>>>(
            p_a3, p_v, p_part, DH_, N_ / 4, N_, DH_, sS1, sQ, sL,
            1.f, nullptr, 0.f, nullptr, nullptr);
        a3v_reduce_kernel<<<(BH_ * M_ * DH_) / 256, 256>>>();
    }

    // 8) w = a2inv @ a3v  (tiny: 256x64x256)
    gemm<0>(p_z0, p_a3v, p_w, M_, DH_, M_, BH_, M_, DH_, sA2, sL, sL, false);

    // 9) ctx = a1 @ w  (reassociated; writes ctx layout directly)
    gemm<2>(p_a1, p_w, nullptr, N_, DH_, M_, BH_, M_, DH_, sS1, sL, 0, false);

    // 10) depthwise conv residual added into ctx
    conv_add_kernel<<<(BH_ * N_ * DH_) / 256, 256>>>(conv_w);

    // 11) output projection + bias + omega * x
    gemm<0>(p_ctx, w_out, out, ROWS_, DIM_, DIM_, 1, DIM_, DIM_, 0, 0, 0, false,
            1.f, x, 0.f, omega, b_out);
}

// round 8
// speedup vs baseline: 2.6944x; 1.0446x over previous
#include <cuda_runtime.h>
#include <cuda_bf16.h>
#include <cstdint>

// ---------------------------------------------------------------------------
// Nystrom attention transformer layer. TF32 mma GEMMs, 64x64 warp tiles,
// 3-stage single-sync cp.async pipeline, conflict-free smem, fused epilogues.
// ---------------------------------------------------------------------------

#define B_    4
#define N_    4096
#define DIM_  512
#define H_    8
#define DH_   64
#define M_    256
#define L_    16
#define ROWS_ (B_ * N_)          // 16384
#define BH_   (B_ * H_)          // 32

// ---------------- scratch (device globals) ----------------------------------
__device__ float g_ln  [ROWS_ * DIM_];
__device__ float g_q   [BH_ * N_ * DH_];
__device__ float g_k   [BH_ * N_ * DH_];
__device__ float g_v   [BH_ * N_ * DH_];
__device__ float g_ql  [BH_ * M_ * DH_];
__device__ float g_kl  [BH_ * M_ * DH_];
__device__ float g_a1  [BH_ * N_ * M_];
__device__ float g_a3  [BH_ * M_ * N_];     // exp(sim3)
__device__ float g_a2  [BH_ * M_ * M_];
__device__ float g_z0  [BH_ * M_ * M_];
__device__ float g_z1  [BH_ * M_ * M_];
__device__ float g_t1  [BH_ * M_ * M_];
__device__ float g_t2  [BH_ * M_ * M_];
__device__ float g_t3  [BH_ * M_ * M_];
__device__ float g_a3v [BH_ * M_ * DH_];
__device__ float g_w   [BH_ * M_ * DH_];    // a2inv @ a3v
__device__ float g_part[BH_ * 4 * M_ * DH_];
__device__ float g_rsum[BH_ * M_];
__device__ float g_ctx [ROWS_ * DIM_];
__device__ float g_max [2];

// ---------------- reductions -------------------------------------------------
__device__ __forceinline__ float blockReduceSum(float v, float* sh) {
    int tid = threadIdx.x;
    sh[tid] = v; __syncthreads();
    for (int s = 128; s > 0; s >>= 1) {
        if (tid < s) sh[tid] += sh[tid + s];
        __syncthreads();
    }
    float r = sh[0]; __syncthreads();
    return r;
}
__device__ __forceinline__ float blockReduceMax(float v, float* sh) {
    int tid = threadIdx.x;
    sh[tid] = v; __syncthreads();
    for (int s = 128; s > 0; s >>= 1) {
        if (tid < s) sh[tid] = fmaxf(sh[tid], sh[tid + s]);
        __syncthreads();
    }
    float r = sh[0]; __syncthreads();
    return r;
}

// ---------------- layernorm --------------------------------------------------
__global__ __launch_bounds__(256) void ln_kernel(
    const float* __restrict__ x, const float* __restrict__ w,
    const float* __restrict__ b)
{
    __shared__ float sh[256];
    long long r = blockIdx.x;
    const float* xr = x + r * DIM_;
    int tid = threadIdx.x;
    float v0 = xr[tid], v1 = xr[tid + 256];
    float s = blockReduceSum(v0 + v1, sh);
    float mu = s * (1.0f / DIM_);
    float d0 = v0 - mu, d1 = v1 - mu;
    float s2 = blockReduceSum(d0 * d0 + d1 * d1, sh);
    float inv = rsqrtf(s2 * (1.0f / DIM_) + 1e-5f);
    g_ln[r * DIM_ + tid]        = d0 * inv * w[tid] + b[tid];
    g_ln[r * DIM_ + tid + 256]  = d1 * inv * w[tid + 256] + b[tid + 256];
}

// ---------------- mma + cp.async helpers -------------------------------------
__device__ __forceinline__ void mma_tf32(
    float& c0, float& c1, float& c2, float& c3,
    uint32_t a0, uint32_t a1, uint32_t a2, uint32_t a3,
    uint32_t b0, uint32_t b1)
{
    asm volatile(
        "mma.sync.aligned.m16n8k8.row.col.f32.tf32.tf32.f32 "
        "{%0,%1,%2,%3}, {%4,%5,%6,%7}, {%8,%9}, {%0,%1,%2,%3};"
        : "+f"(c0), "+f"(c1), "+f"(c2), "+f"(c3)
        : "r"(a0), "r"(a1), "r"(a2), "r"(a3), "r"(b0), "r"(b1));
}
__device__ __forceinline__ void cpa16(void* dst, const void* src) {
    uint32_t d = (uint32_t)__cvta_generic_to_shared(dst);
    asm volatile("cp.async.cg.shared.global [%0], [%1], 16;" :: "r"(d), "l"(src));
}
#define CP_COMMIT() asm volatile("cp.async.commit_group;" ::: "memory")
#define CP_WAIT1()  asm volatile("cp.async.wait_group 1;" ::: "memory")
#define CP_WAIT0()  asm volatile("cp.async.wait_group 0;" ::: "memory")

#define BK2 16
#define RS  20      // [row][k] stride (words): frag banks 20g+tg = all 32 distinct

// ---------------- main mma GEMM: 128 threads, 2x2 warps, 64x64 warp tile -----
// 3-stage cp.async pipeline, ONE __syncthreads per k-iteration.
// MODE 0: standard epilogue; MODE 1: qkv split; MODE 2: ctx layout;
// MODE 3: exp + atomic row sums (for sim3).
// SPLITK: blockIdx.z = bh*4 + split, Kdim = chunk length.
template<int BM, int BN, bool TB, int MODE, bool SPLITK>
__global__ __launch_bounds__(128, 2) void mma_gemm_kernel(
    const float* __restrict__ A, const float* __restrict__ B,
    float* __restrict__ C, int Ndim, int Kdim, int ldA, int ldB,
    long long sA, long long sB, long long sC,
    float alpha,
    const float* __restrict__ resid, float residScale,
    const float* __restrict__ residScalePtr,
    const float* __restrict__ bias)
{
    constexpr int MT = 4;               // 64 rows / 16
    constexpr int NT = BN / 16;         // (BN/2) / 8
    constexpr int RSB = BN + 8;         // [k][n] stride: frag banks 8tg+g distinct
    constexpr int ASZ = BM * RS;
    constexpr int BSZ = TB ? BN * RS : BK2 * RSB;
    constexpr int STG = ASZ + BSZ;

    extern __shared__ __align__(16) float smp[];   // 3 stages

    int bz = blockIdx.z;
    long long aOff, bOff, cOff;
    if (SPLITK) {
        int bz0 = bz >> 2, sp = bz & 3;
        aOff = (long long)bz0 * sA + (long long)sp * Kdim;
        bOff = (long long)bz0 * sB + (long long)sp * Kdim * ldB;
        cOff = (long long)bz * sC;
    } else {
        aOff = (long long)bz * sA;
        bOff = (long long)bz * sB;
        cOff = (long long)bz * sC;
    }
    const float* Ab = A + aOff;
    const float* Bb = B + bOff;
    float*       Cb = C + cOff;
    const float* Rb = resid ? resid + cOff : nullptr;

    int n0 = blockIdx.x * BN;
    int m0 = blockIdx.y * BM;
    int tid  = threadIdx.x;
    int wid  = tid >> 5;
    int lane = tid & 31;
    int wm = wid >> 1, wn = wid & 1;
    int tm0 = wm * 64, tn0 = wn * (BN / 2);
    int g  = lane >> 2;
    int tg = lane & 3;

    float acc[MT][NT][4];
    #pragma unroll
    for (int i = 0; i < MT; i++)
        #pragma unroll
        for (int j = 0; j < NT; j++)
            #pragma unroll
            for (int c = 0; c < 4; c++) acc[i][j][c] = 0.f;

    auto loadTile = [&](int t, int st) {
        int k0 = t * BK2;
        float* As = smp + st * STG;
        float* Bs = As + ASZ;
        #pragma unroll
        for (int c = 0; c < BM / 32; c++) {
            int id = c * 128 + tid;
            int m = id >> 2, kq = (id & 3) * 4;
            cpa16(&As[m * RS + kq],
                  Ab + (long long)(m0 + m) * ldA + k0 + kq);
        }
        if (TB) {
            #pragma unroll
            for (int c = 0; c < BN / 32; c++) {
                int id = c * 128 + tid;
                int n = id >> 2, kq = (id & 3) * 4;
                cpa16(&Bs[n * RS + kq],
                      Bb + (long long)(n0 + n) * ldB + k0 + kq);
            }
        } else {
            constexpr int CPR = BN / 4;   // 16B chunks per k-row
            #pragma unroll
            for (int c = 0; c < BN / 32; c++) {
                int id = c * 128 + tid;
                int k = id / CPR, nq = (id % CPR) * 4;
                cpa16(&Bs[k * RSB + nq],
                      Bb + (long long)(k0 + k) * ldB + n0 + nq);
            }
        }
    };

    auto computeStage = [&](int st) {
        const float* as = smp + st * STG;
        const float* bs = as + ASZ;
        #pragma unroll
        for (int kk = 0; kk < BK2; kk += 8) {
            int c0 = kk + tg, c1 = c0 + 4;
            uint32_t af[MT][4], bf[NT][2];
            #pragma unroll
            for (int i = 0; i < MT; i++) {
                int r0 = (tm0 + i * 16 + g) * RS;
                int r1 = r0 + 8 * RS;
                af[i][0] = __float_as_uint(as[r0 + c0]);
                af[i][1] = __float_as_uint(as[r1 + c0]);
                af[i][2] = __float_as_uint(as[r0 + c1]);
                af[i][3] = __float_as_uint(as[r1 + c1]);
            }
            #pragma unroll
            for (int j = 0; j < NT; j++) {
                if (TB) {
                    int rn = (tn0 + j * 8 + g) * RS;
                    bf[j][0] = __float_as_uint(bs[rn + c0]);
                    bf[j][1] = __float_as_uint(bs[rn + c1]);
                } else {
                    int b0 = c0 * RSB + tn0 + j * 8 + g;
                    bf[j][0] = __float_as_uint(bs[b0]);
                    bf[j][1] = __float_as_uint(bs[b0 + 4 * RSB]);
                }
            }
            #pragma unroll
            for (int i = 0; i < MT; i++)
                #pragma unroll
                for (int j = 0; j < NT; j++)
                    mma_tf32(acc[i][j][0], acc[i][j][1], acc[i][j][2], acc[i][j][3],
                             af[i][0], af[i][1], af[i][2], af[i][3],
                             bf[j][0], bf[j][1]);
        }
    };

    int nIter = Kdim / BK2;
    loadTile(0, 0); CP_COMMIT();
    loadTile(1, 1); CP_COMMIT();
    int p = 0;
    for (int t = 0; t < nIter; t++) {
        CP_WAIT1();
        __syncthreads();
        // Load into stage (t+2)%3 == (t-1)%3, whose consumers all passed the
        // barrier above -> safe with a single sync per iteration (3 stages).
        if (t + 2 < nIter) {
            int st = p + 2; if (st >= 3) st -= 3;
            loadTile(t + 2, st);
        }
        CP_COMMIT();
        computeStage(p);
        p = (p + 1 == 3) ? 0 : p + 1;
    }

    // ---------------- epilogue ----------------
    if (MODE == 3) {
        #pragma unroll
        for (int i = 0; i < MT; i++) {
            int r0 = m0 + tm0 + i * 16 + g;
            int r1 = r0 + 8;
            float s0 = 0.f, s1 = 0.f;
            #pragma unroll
            for (int j = 0; j < NT; j++) {
                int cc = n0 + tn0 + j * 8 + tg * 2;
                float e0 = __expf(acc[i][j][0]);
                float e1 = __expf(acc[i][j][1]);
                float e2 = __expf(acc[i][j][2]);
                float e3 = __expf(acc[i][j][3]);
                *(float2*)(Cb + (long long)r0 * Ndim + cc) = make_float2(e0, e1);
                *(float2*)(Cb + (long long)r1 * Ndim + cc) = make_float2(e2, e3);
                s0 += e0 + e1; s1 += e2 + e3;
            }
            s0 += __shfl_xor_sync(0xffffffffu, s0, 1);
            s0 += __shfl_xor_sync(0xffffffffu, s0, 2);
            s1 += __shfl_xor_sync(0xffffffffu, s1, 1);
            s1 += __shfl_xor_sync(0xffffffffu, s1, 2);
            if (tg == 0) {
                atomicAdd(&g_rsum[bz * M_ + r0], s0);
                atomicAdd(&g_rsum[bz * M_ + r1], s1);
            }
        }
        return;
    }

    float rs = residScalePtr ? *residScalePtr : residScale;
    #pragma unroll
    for (int i = 0; i < MT; i++) {
        int r0 = m0 + tm0 + i * 16 + g;
        int r1 = r0 + 8;
        #pragma unroll
        for (int j = 0; j < NT; j++) {
            int cc = n0 + tn0 + j * 8 + tg * 2;
            if (MODE == 0) {
                float2 bv = bias ? *(const float2*)(bias + cc) : make_float2(0.f, 0.f);
                float2 v0 = make_float2(alpha * acc[i][j][0] + bv.x,
                                        alpha * acc[i][j][1] + bv.y);
                float2 v1 = make_float2(alpha * acc[i][j][2] + bv.x,
                                        alpha * acc[i][j][3] + bv.y);
                if (Rb) {
                    float2 q0 = *(const float2*)(Rb + (long long)r0 * Ndim + cc);
                    float2 q1 = *(const float2*)(Rb + (long long)r1 * Ndim + cc);
                    v0.x += rs * q0.x; v0.y += rs * q0.y;
                    v1.x += rs * q1.x; v1.y += rs * q1.y;
                }
                *(float2*)(Cb + (long long)r0 * Ndim + cc) = v0;
                *(float2*)(Cb + (long long)r1 * Ndim + cc) = v1;
            } else if (MODE == 1) {
                int which = cc >> 9;
                int hc = cc & 511;
                int h = hc >> 6, d = hc & 63;
                float sc = (which == 0) ? 0.125f : 1.0f;
                float* dstbuf = (which == 0) ? g_q : (which == 1) ? g_k : g_v;
                #pragma unroll
                for (int rr = 0; rr < 2; rr++) {
                    int row = rr ? r1 : r0;
                    int b = row >> 12, nn = row & 4095;
                    long long dst = (((long long)((b << 3) + h)) * N_ + nn) * DH_ + d;
                    float2 v = rr ? make_float2(sc * acc[i][j][2], sc * acc[i][j][3])
                                  : make_float2(sc * acc[i][j][0], sc * acc[i][j][1]);
                    *(float2*)(dstbuf + dst) = v;
                }
            } else {
                int b = bz >> 3, h = bz & 7;
                *(float2*)(g_ctx + ((long long)(b * N_ + r0)) * DIM_ + h * DH_ + cc) =
                    make_float2(acc[i][j][0], acc[i][j][1]);
                *(float2*)(g_ctx + ((long long)(b * N_ + r1)) * DIM_ + h * DH_ + cc) =
                    make_float2(acc[i][j][2], acc[i][j][3]);
            }
        }
    }
}

// ---------------- sim GEMM (TB) with fused full-row softmax ------------------
__global__ __launch_bounds__(256) void sim_softmax_kernel(
    const float* __restrict__ A, const float* __restrict__ Bm,
    float* __restrict__ C, int Kdim,
    long long sA, long long sB, long long sC)
{
    constexpr int BMs = 64, BNs = 256;
    __shared__ __align__(16) float As[BMs * RS];
    __shared__ __align__(16) float Bs[BNs * RS];
    __shared__ float redM[4][BMs];
    __shared__ float redS[4][BMs];

    int bz = blockIdx.z;
    const float* Ab = A + (long long)bz * sA;
    const float* Bb = Bm + (long long)bz * sB;
    float*       Cb = C + (long long)bz * sC;

    int m0 = blockIdx.y * BMs;
    int tid  = threadIdx.x;
    int wid  = tid >> 5;
    int lane = tid & 31;
    int wm = wid >> 2, wn = wid & 3;
    int tm0 = wm * 32, tn0 = wn * 64;
    int g  = lane >> 2;
    int tg = lane & 3;

    float acc[2][8][4];
    #pragma unroll
    for (int i = 0; i < 2; i++)
        #pragma unroll
        for (int j = 0; j < 8; j++)
            #pragma unroll
            for (int c = 0; c < 4; c++) acc[i][j][c] = 0.f;

    for (int k0 = 0; k0 < Kdim; k0 += BK2) {
        {
            int m = tid >> 2, kq = (tid & 3) * 4;
            cpa16(&As[m * RS + kq], Ab + (long long)(m0 + m) * Kdim + k0 + kq);
        }
        #pragma unroll
        for (int c = 0; c < 4; c++) {
            int id = c * 256 + tid;
            int n = id >> 2, kq = (id & 3) * 4;
            cpa16(&Bs[n * RS + kq], Bb + (long long)n * Kdim + k0 + kq);
        }
        CP_COMMIT();
        CP_WAIT0();
        __syncthreads();

        #pragma unroll
        for (int kk = 0; kk < BK2; kk += 8) {
            int c0 = kk + tg, c1 = c0 + 4;
            uint32_t af[2][4], bf[8][2];
            #pragma unroll
            for (int i = 0; i < 2; i++) {
                int r0 = (tm0 + i * 16 + g) * RS;
                int r1 = r0 + 8 * RS;
                af[i][0] = __float_as_uint(As[r0 + c0]);
                af[i][1] = __float_as_uint(As[r1 + c0]);
                af[i][2] = __float_as_uint(As[r0 + c1]);
                af[i][3] = __float_as_uint(As[r1 + c1]);
            }
            #pragma unroll
            for (int j = 0; j < 8; j++) {
                int rn = (tn0 + j * 8 + g) * RS;
                bf[j][0] = __float_as_uint(Bs[rn + c0]);
                bf[j][1] = __float_as_uint(Bs[rn + c1]);
            }
            #pragma unroll
            for (int i = 0; i < 2; i++)
                #pragma unroll
                for (int j = 0; j < 8; j++)
                    mma_tf32(acc[i][j][0], acc[i][j][1], acc[i][j][2], acc[i][j][3],
                             af[i][0], af[i][1], af[i][2], af[i][3],
                             bf[j][0], bf[j][1]);
        }
        __syncthreads();
    }

    #pragma unroll
    for (int i = 0; i < 2; i++) {
        float mx0 = -1e30f, mx1 = -1e30f;
        #pragma unroll
        for (int j = 0; j < 8; j++) {
            mx0 = fmaxf(mx0, fmaxf(acc[i][j][0], acc[i][j][1]));
            mx1 = fmaxf(mx1, fmaxf(acc[i][j][2], acc[i][j][3]));
        }
        mx0 = fmaxf(mx0, __shfl_xor_sync(0xffffffffu, mx0, 1));
        mx0 = fmaxf(mx0, __shfl_xor_sync(0xffffffffu, mx0, 2));
        mx1 = fmaxf(mx1, __shfl_xor_sync(0xffffffffu, mx1, 1));
        mx1 = fmaxf(mx1, __shfl_xor_sync(0xffffffffu, mx1, 2));
        if (tg == 0) {
            redM[wn][tm0 + i * 16 + g]     = mx0;
            redM[wn][tm0 + i * 16 + g + 8] = mx1;
        }
    }
    __syncthreads();
    #pragma unroll
    for (int i = 0; i < 2; i++) {
        int rb0 = tm0 + i * 16 + g, rb1 = rb0 + 8;
        float mx0 = fmaxf(fmaxf(redM[0][rb0], redM[1][rb0]),
                          fmaxf(redM[2][rb0], redM[3][rb0]));
        float mx1 = fmaxf(fmaxf(redM[0][rb1], redM[1][rb1]),
                          fmaxf(redM[2][rb1], redM[3][rb1]));
        float s0 = 0.f, s1 = 0.f;
        #pragma unroll
        for (int j = 0; j < 8; j++) {
            float e0 = __expf(acc[i][j][0] - mx0);
            float e1 = __expf(acc[i][j][1] - mx0);
            float e2 = __expf(acc[i][j][2] - mx1);
            float e3 = __expf(acc[i][j][3] - mx1);
            acc[i][j][0] = e0; acc[i][j][1] = e1;
            acc[i][j][2] = e2; acc[i][j][3] = e3;
            s0 += e0 + e1; s1 += e2 + e3;
        }
        s0 += __shfl_xor_sync(0xffffffffu, s0, 1);
        s0 += __shfl_xor_sync(0xffffffffu, s0, 2);
        s1 += __shfl_xor_sync(0xffffffffu, s1, 1);
        s1 += __shfl_xor_sync(0xffffffffu, s1, 2);
        if (tg == 0) { redS[wn][rb0] = s0; redS[wn][rb1] = s1; }
    }
    __syncthreads();
    #pragma unroll
    for (int i = 0; i < 2; i++) {
        int rb0 = tm0 + i * 16 + g, rb1 = rb0 + 8;
        float i0 = 1.f / (redS[0][rb0] + redS[1][rb0] + redS[2][rb0] + redS[3][rb0]);
        float i1 = 1.f / (redS[0][rb1] + redS[1][rb1] + redS[2][rb1] + redS[3][rb1]);
        int r0 = m0 + rb0, r1 = m0 + rb1;
        #pragma unroll
        for (int j = 0; j < 8; j++) {
            int cc = tn0 + j * 8 + tg * 2;
            *(float2*)(Cb + (long long)r0 * 256 + cc) =
                make_float2(acc[i][j][0] * i0, acc[i][j][1] * i0);
            *(float2*)(Cb + (long long)r1 * 256 + cc) =
                make_float2(acc[i][j][2] * i1, acc[i][j][3] * i1);
        }
    }
}

// ---------------- landmark means ---------------------------------------------
__global__ __launch_bounds__(256) void landmark_kernel()
{
    int id = blockIdx.x * 256 + threadIdx.x;
    const int half = BH_ * M_ * DH_;
    bool isK = id >= half;
    int t = isK ? id - half : id;
    int d  = t & 63;
    int m  = (t >> 6) & 255;
    int bh = t >> 14;
    const float* src = (isK ? g_k : g_q) + ((long long)bh * N_ + m * L_) * DH_ + d;
    float s = 0.f;
    #pragma unroll
    for (int l = 0; l < L_; l++) s += src[l * DH_];
    (isK ? g_kl : g_ql)[t] = s * (1.0f / L_);
}

// ---------------- zero rsum ---------------------------------------------------
__global__ __launch_bounds__(256) void zero_rsum_kernel()
{
    g_rsum[blockIdx.x * 256 + threadIdx.x] = 0.f;
}

// ---------------- a3v split-K reduce + row normalize -------------------------
__global__ __launch_bounds__(256) void a3v_reduce_kernel()
{
    int idx = blockIdx.x * 256 + threadIdx.x;
    int rrow = idx >> 6;
    int bh = idx >> 14;
    int inner = idx & 16383;
    long long base = (long long)bh * 4 * 16384 + inner;
    float s = g_part[base] + g_part[base + 16384]
            + g_part[base + 2 * 16384] + g_part[base + 3 * 16384];
    g_a3v[idx] = s / g_rsum[rrow];
}

// ---------------- pinv init ---------------------------------------------------
__global__ void zero_max_kernel() { g_max[0] = 0.f; g_max[1] = 0.f; }

__global__ __launch_bounds__(256) void pinv_absmax_kernel()
{
    __shared__ float sh[256];
    const float* X = g_a2 + (long long)blockIdx.x * (M_ * M_);
    int tid = threadIdx.x;
    float cs = 0.f, rs = 0.f;
    for (int j = 0; j < M_; j++) cs += fabsf(X[tid * M_ + j]);
    for (int i = 0; i < M_; i++) rs += fabsf(X[i * M_ + tid]);
    float cm = blockReduceMax(cs, sh);
    float rm = blockReduceMax(rs, sh);
    if (tid == 0) {
        atomicMax(reinterpret_cast<int*>(&g_max[0]), __float_as_int(cm));
        atomicMax(reinterpret_cast<int*>(&g_max[1]), __float_as_int(rm));
    }
}

__global__ __launch_bounds__(256) void zinit_kernel()
{
    long long id = (long long)blockIdx.x * 256 + threadIdx.x;
    float inv = 1.0f / (g_max[0] * g_max[1]);
    long long bh = id >> 16;
    int rem = (int)(id & 65535);
    int row = rem >> 8, col = rem & 255;
    g_z0[id] = g_a2[bh * (M_ * M_) + (long long)col * M_ + row] * inv;
}

// ---------------- depthwise conv residual added into ctx (smem tiled) ---------
// grid: BH_ * (N_/128) blocks of 256 threads. 160-row x 64-d input tile in smem.
__global__ __launch_bounds__(256) void conv_add_kernel(const float* __restrict__ cw)
{
    __shared__ __align__(16) float sv[160 * 64];

    int bid = blockIdx.x;
    int bh = bid >> 5;              // N_/128 = 32 tiles per bh
    int tile = bid & 31;
    int n0 = tile * 128;
    int h = bh & 7, b = bh >> 3;
    int tid = threadIdx.x;
    const float* vb = g_v + ((long long)bh << 18);

    // load rows [n0-16, n0+144) x 64 (zero-pad outside [0, N))
    #pragma unroll
    for (int c = 0; c < 10; c++) {
        int e = (c * 256 + tid) * 4;       // 2560 float4 chunks
        int r = e >> 6, d = e & 63;
        int gr = n0 - 16 + r;
        float4 val = make_float4(0.f, 0.f, 0.f, 0.f);
        if ((unsigned)gr < (unsigned)N_)
            val = *(const float4*)(vb + (long long)gr * DH_ + d);
        *(float4*)(sv + r * 64 + d) = val;
    }
    __syncthreads();

    int d = tid & 63, rg = tid >> 6;       // 4 row-groups of 32 output rows
    float wr[33];
    #pragma unroll
    for (int k = 0; k < 33; k++) wr[k] = cw[h * 33 + k];

    #pragma unroll
    for (int half = 0; half < 2; half++) {
        int ob = rg * 32 + half * 16;      // local output rows ob..ob+15
        float in[48];
        #pragma unroll
        for (int j = 0; j < 48; j++) in[j] = sv[(ob + j) * 64 + d];
        #pragma unroll
        for (int i = 0; i < 16; i++) {
            float acc = 0.f;
            #pragma unroll
            for (int k = 0; k < 33; k++) acc += wr[k] * in[i + k];
            int grow = n0 + ob + i;
            g_ctx[((long long)(b * N_ + grow)) * DIM_ + h * DH_ + d] += acc;
        }
    }
}

// ---------------- host helpers -------------------------------------------------
static float* symaddr(const void* sym) {
    void* p = nullptr;
    cudaGetSymbolAddress(&p, sym);
    return (float*)p;
}

template<int BM, int BN, bool TB, int MODE, bool SPLITK>
static void launch_gemm(dim3 grid,
                 const float* A, const float* B, float* C,
                 int N, int K, int ldA, int ldB,
                 long long sA, long long sB, long long sC,
                 float alpha, const float* resid, float rs,
                 const float* rsPtr, const float* bias)
{
    constexpr int RSB = BN + 8;
    constexpr int ASZ = BM * RS;
    constexpr int BSZ = TB ? BN * RS : BK2 * RSB;
    int smem = 3 * (ASZ + BSZ) * 4;
    auto kfn = mma_gemm_kernel<BM, BN, TB, MODE, SPLITK>;
    cudaFuncSetAttribute(kfn, cudaFuncAttributeMaxDynamicSharedMemorySize, smem);
    kfn<<<grid, 128, smem>>>(A, B, C, N, K, ldA, ldB, sA, sB, sC,
                             alpha, resid, rs, rsPtr, bias);
}

template<int MODE>
static void gemm(const float* A, const float* B, float* C,
                 int M, int N, int K, int batch, int ldA, int ldB,
                 long long sA, long long sB, long long sC, bool tb,
                 float alpha = 1.f,
                 const float* resid = nullptr, float rs = 0.f,
                 const float* rsPtr = nullptr,
                 const float* bias = nullptr,
                 bool forceBN64 = false)
{
    if (N % 128 == 0 && !forceBN64) {
        dim3 grid(N / 128, M / 128, batch);
        if (tb)
            launch_gemm<128, 128, true , MODE, false>(grid, A, B, C, N, K,
                ldA, ldB, sA, sB, sC, alpha, resid, rs, rsPtr, bias);
        else
            launch_gemm<128, 128, false, MODE, false>(grid, A, B, C, N, K,
                ldA, ldB, sA, sB, sC, alpha, resid, rs, rsPtr, bias);
    } else {
        dim3 grid(N / 64, M / 128, batch);
        if (tb)
            launch_gemm<128, 64, true , MODE, false>(grid, A, B, C, N, K,
                ldA, ldB, sA, sB, sC, alpha, resid, rs, rsPtr, bias);
        else
            launch_gemm<128, 64, false, MODE, false>(grid, A, B, C, N, K,
                ldA, ldB, sA, sB, sC, alpha, resid, rs, rsPtr, bias);
    }
}

extern "C" void kernel_launch(void* const* d_in, const int* in_sizes, int n_in,
                              void* d_out, int out_size)
{
    const float* x      = (const float*)d_in[0];
    const float* ln_w   = (const float*)d_in[1];
    const float* ln_b   = (const float*)d_in[2];
    const float* w_qkv  = (const float*)d_in[3];
    const float* w_out  = (const float*)d_in[4];
    const float* b_out  = (const float*)d_in[5];
    const float* conv_w = (const float*)d_in[6];
    const float* omega  = (const float*)d_in[7];
    float* out = (float*)d_out;

    float* p_ln   = symaddr(g_ln);
    float* p_q    = symaddr(g_q);
    float* p_k    = symaddr(g_k);
    float* p_v    = symaddr(g_v);
    float* p_ql   = symaddr(g_ql);
    float* p_kl   = symaddr(g_kl);
    float* p_a1   = symaddr(g_a1);
    float* p_a3   = symaddr(g_a3);
    float* p_a2   = symaddr(g_a2);
    float* p_z0   = symaddr(g_z0);
    float* p_z1   = symaddr(g_z1);
    float* p_t1   = symaddr(g_t1);
    float* p_t2   = symaddr(g_t2);
    float* p_t3   = symaddr(g_t3);
    float* p_a3v  = symaddr(g_a3v);
    float* p_w    = symaddr(g_w);
    float* p_part = symaddr(g_part);
    float* p_ctx  = symaddr(g_ctx);

    const long long sQ  = (long long)N_ * DH_;
    const long long sL  = (long long)M_ * DH_;
    const long long sS1 = (long long)N_ * M_;
    const long long sA2 = (long long)M_ * M_;

    // 1) layernorm
    ln_kernel<<<ROWS_, 256>>>(x, ln_w, ln_b);

    // 2) qkv projection, epilogue writes q (scaled), k, v head-major
    gemm<1>(p_ln, w_qkv, nullptr, ROWS_, 3 * DIM_, DIM_, 1, DIM_, 3 * DIM_,
            0, 0, 0, false);

    // 3) landmarks
    landmark_kernel<<<(2 * BH_ * M_ * DH_) / 256, 256>>>();

    // 4) sim1 + softmax -> a1; sim2 + softmax -> a2
    {
        dim3 block(256);
        sim_softmax_kernel<<<dim3(1, N_ / 64, BH_), block>>>(
            p_q, p_kl, p_a1, DH_, sQ, sL, sS1);
        sim_softmax_kernel<<<dim3(1, M_ / 64, BH_), block>>>(
            p_ql, p_kl, p_a2, DH_, sL, sL, sA2);
    }

    // 5) sim3 -> exp(sim3) with fused row sums
    zero_rsum_kernel<<<(BH_ * M_) / 256, 256>>>();
    gemm<3>(p_ql, p_k, p_a3, M_, N_, DH_, BH_, DH_, DH_, sL, sQ, sS1, true);

    // 6) Moore-Penrose pinv of a2 (Newton-Schulz, 6 iters), BN=64
    zero_max_kernel<<<1, 1>>>();
    pinv_absmax_kernel<<<BH_, 256>>>();
    zinit_kernel<<<(BH_ * M_ * M_) / 256, 256>>>();

    for (int it = 0; it < 6; it++) {
        float* zin  = (it & 1) ? p_z1 : p_z0;
        float* zout = (it & 1) ? p_z0 : p_z1;
        gemm<0>(p_a2, zin, p_t1, M_, M_, M_, BH_, M_, M_, sA2, sA2, sA2, false,
                1.f, nullptr, 0.f, nullptr, nullptr, true);
        gemm<0>(p_t1, p_t1, p_t2, M_, M_, M_, BH_, M_, M_, sA2, sA2, sA2, false,
                -1.f, p_t1, 7.f, nullptr, nullptr, true);
        gemm<0>(p_t1, p_t2, p_t3, M_, M_, M_, BH_, M_, M_, sA2, sA2, sA2, false,
                -1.f, p_t1, 15.f, nullptr, nullptr, true);
        gemm<0>(zin, p_t3, zout, M_, M_, M_, BH_, M_, M_, sA2, sA2, sA2, false,
                -0.25f, zin, 3.25f, nullptr, nullptr, true);
    }

    // 7) a3v = (exp(sim3) @ v) / rowsum, split-K x4
    {
        dim3 grid(1, M_ / 128, BH_ * 4);
        launch_gemm<128, 64, false, 0, true>(grid, p_a3, p_v, p_part,
            DH_, N_ / 4, N_, DH_, sS1, sQ, sL,
            1.f, nullptr, 0.f, nullptr, nullptr);
        a3v_reduce_kernel<<<(BH_ * M_ * DH_) / 256, 256>>>();
    }

    // 8) w = a2inv @ a3v  (tiny: 256x64x256)
    gemm<0>(p_z0, p_a3v, p_w, M_, DH_, M_, BH_, M_, DH_, sA2, sL, sL, false);

    // 9) ctx = a1 @ w  (reassociated; writes ctx layout directly)
    gemm<2>(p_a1, p_w, nullptr, N_, DH_, M_, BH_, M_, DH_, sS1, sL, 0, false);

    // 10) depthwise conv residual added into ctx (smem tiled)
    conv_add_kernel<<<BH_ * (N_ / 128), 256>>>(conv_w);

    // 11) output projection + bias + omega * x
    gemm<0>(p_ctx, w_out, out, ROWS_, DIM_, DIM_, 1, DIM_, DIM_, 0, 0, 0, false,
            1.f, x, 0.f, omega, b_out);
}